// round 1
// baseline (speedup 1.0000x reference)
#include <cuda_runtime.h>
#include <cstdint>

#define H_  32
#define N_  2048
#define T_  2048
#define D_  128
#define R_  64

// scratch: effective K (k_quant + JL sign correction), 32*2048*128 fp32 = 33.5 MB
__device__ float g_keff[H_ * T_ * D_];

// ---------------------------------------------------------------------------
// Prep kernel: per head, per 64-token chunk:
//   s[t,r]    = sign( sum_d (k_orig-k_quant)[t,d] * G[d,r] )     (exact fp32!)
//   keff[t,d] = k_quant[t,d] + (1/64) * sum_r G[d,r] * s[t,r]
// ---------------------------------------------------------------------------
#define SG_S  68   // sG  [128][68]  (row d, cols r)
#define SGT_S 132  // sGT [64][132]  (row r, cols d)
#define SE_S  65   // sE  [128][65]  (row d, cols t)
#define SS_S  68   // sS  [64][68]   (row r, cols t)  -- aliases sE region

__global__ void qjl_prep_kernel(const float* __restrict__ k_orig,
                                const float* __restrict__ k_quant,
                                const float* __restrict__ G)
{
    extern __shared__ float sm[];
    float* sG  = sm;                        // 128*68 = 8704 floats
    float* sGT = sG + 128 * SG_S;           // 64*132 = 8448 floats
    float* sE  = sGT + 64 * SGT_S;          // 128*65 = 8320 floats
    float* sS  = sE;                        // 64*68  = 4352 floats (reuse)

    const int tid = threadIdx.x;
    const int h   = blockIdx.y;
    const int t0  = blockIdx.x * 64;

    // Load G into both layouts
    for (int i = tid; i < D_ * R_; i += 256) {
        int d = i >> 6, r = i & 63;
        float g = G[i];                     // G is [D][R] row-major
        sG [d * SG_S  + r] = g;
        sGT[r * SGT_S + d] = g;
    }
    // Load residual e = k_orig - k_quant, transposed: sE[d][t]
    const float* ko = k_orig  + ((size_t)h * T_ + t0) * D_;
    const float* kq = k_quant + ((size_t)h * T_ + t0) * D_;
    for (int i = tid; i < 64 * D_; i += 256) {
        int t = i >> 7, d = i & 127;
        sE[d * SE_S + t] = ko[t * D_ + d] - kq[t * D_ + d];
    }
    __syncthreads();

    // ---- stage 1: s = sign(e @ G), thread = (tc = tid&63, rg = tid>>6), 16 r's each
    {
        const int tc = tid & 63;
        const int rg = tid >> 6;
        float acc[16];
        #pragma unroll
        for (int i = 0; i < 16; i++) acc[i] = 0.f;
        for (int d = 0; d < D_; d++) {
            float ev = sE[d * SE_S + tc];
            const float4* gp = (const float4*)(sG + d * SG_S + rg * 16);
            #pragma unroll
            for (int v = 0; v < 4; v++) {
                float4 g4 = gp[v];
                acc[v*4+0] += ev * g4.x;
                acc[v*4+1] += ev * g4.y;
                acc[v*4+2] += ev * g4.z;
                acc[v*4+3] += ev * g4.w;
            }
        }
        __syncthreads();   // all reads of sE done before sS (alias) is written
        #pragma unroll
        for (int i = 0; i < 16; i++) {
            float s = (acc[i] > 0.f) ? 1.f : ((acc[i] < 0.f) ? -1.f : 0.f);
            sS[(rg * 16 + i) * SS_S + tc] = s;
        }
    }
    __syncthreads();

    // ---- stage 2: keff = k_quant + (G @ s^T)/64, thread = (d = tid&127, tcg = tid>>7)
    {
        const int d   = tid & 127;
        const int tcg = tid >> 7;
        float acc[32];
        #pragma unroll
        for (int j = 0; j < 32; j++) acc[j] = 0.f;
        for (int r = 0; r < R_; r++) {
            float gv = sGT[r * SGT_S + d];
            const float4* sp = (const float4*)(sS + r * SS_S + tcg * 32);
            #pragma unroll
            for (int v = 0; v < 8; v++) {
                float4 s4 = sp[v];
                acc[v*4+0] += gv * s4.x;
                acc[v*4+1] += gv * s4.y;
                acc[v*4+2] += gv * s4.z;
                acc[v*4+3] += gv * s4.w;
            }
        }
        float* ke = g_keff + ((size_t)h * T_ + t0) * D_;
        const float scale = 1.f / 64.f;
        #pragma unroll
        for (int j = 0; j < 32; j++) {
            int t = tcg * 32 + j;
            ke[t * D_ + d] = kq[t * D_ + d] + acc[j] * scale;
        }
    }
}

// ---------------------------------------------------------------------------
// Main GEMM: out[h, n, t] = sum_d q[h,n,d] * keff[h,t,d]   (tf32 mma.sync)
// Block tile 128x128, BK=16, 256 threads (8 warps, 2x4), warp tile 64x32.
// ---------------------------------------------------------------------------
#define BK  16
#define SMS 132   // smem "row" length in the [k][m] layout (pad 4 -> conflict-free frags)

__device__ __forceinline__ uint32_t f2tf(float x) {
    uint32_t y;
    asm("cvt.rna.tf32.f32 %0, %1;" : "=r"(y) : "f"(x));
    return y;
}

__device__ __forceinline__ void mma_tf32(float* c, const uint32_t* a, const uint32_t* b) {
    asm volatile(
        "mma.sync.aligned.m16n8k8.row.col.f32.tf32.tf32.f32 "
        "{%0,%1,%2,%3}, {%4,%5,%6,%7}, {%8,%9}, {%0,%1,%2,%3};\n"
        : "+f"(c[0]), "+f"(c[1]), "+f"(c[2]), "+f"(c[3])
        : "r"(a[0]), "r"(a[1]), "r"(a[2]), "r"(a[3]), "r"(b[0]), "r"(b[1]));
}

__global__ __launch_bounds__(256) void qjl_gemm_kernel(const float* __restrict__ q,
                                                       float* __restrict__ out)
{
    __shared__ uint32_t sA[2][BK][SMS];   // [stage][k][m], tf32 bits
    __shared__ uint32_t sB[2][BK][SMS];   // [stage][k][n]

    const int tid  = threadIdx.x;
    const int warp = tid >> 5;
    const int lane = tid & 31;
    const int h  = blockIdx.z;
    const int n0 = blockIdx.y * 128;
    const int t0 = blockIdx.x * 128;

    const float* Ag = q      + ((size_t)h * N_ + n0) * D_;
    const float* Bg = g_keff + ((size_t)h * T_ + t0) * D_;

    // loader: thread -> (row = tid>>2, kq0 = (tid&3)*4), plus row+64 for 2nd half
    const int lrow = tid >> 2;
    const int kq0  = (tid & 3) * 4;

    float4 rA[2], rB[2];

    const int warp_m = (warp & 1) * 64;
    const int warp_n = (warp >> 1) * 32;
    const int lr = lane >> 2;
    const int lc = lane & 3;

    float acc[4][4][4];
    #pragma unroll
    for (int mi = 0; mi < 4; mi++)
        #pragma unroll
        for (int ni = 0; ni < 4; ni++)
            #pragma unroll
            for (int v = 0; v < 4; v++) acc[mi][ni][v] = 0.f;

    // prologue: load + store stage 0
    {
        const float* ap = Ag + (size_t)lrow * D_ + kq0;
        const float* bp = Bg + (size_t)lrow * D_ + kq0;
        rA[0] = *(const float4*)ap;
        rA[1] = *(const float4*)(ap + 64 * D_);
        rB[0] = *(const float4*)bp;
        rB[1] = *(const float4*)(bp + 64 * D_);
    }
    #pragma unroll
    for (int hf = 0; hf < 2; hf++) {
        int row = lrow + hf * 64;
        sA[0][kq0+0][row] = f2tf(hf ? rA[1].x : rA[0].x);
        sA[0][kq0+1][row] = f2tf(hf ? rA[1].y : rA[0].y);
        sA[0][kq0+2][row] = f2tf(hf ? rA[1].z : rA[0].z);
        sA[0][kq0+3][row] = f2tf(hf ? rA[1].w : rA[0].w);
        sB[0][kq0+0][row] = f2tf(hf ? rB[1].x : rB[0].x);
        sB[0][kq0+1][row] = f2tf(hf ? rB[1].y : rB[0].y);
        sB[0][kq0+2][row] = f2tf(hf ? rB[1].z : rB[0].z);
        sB[0][kq0+3][row] = f2tf(hf ? rB[1].w : rB[0].w);
    }
    __syncthreads();

    #pragma unroll 1
    for (int kt = 0; kt < D_ / BK; kt++) {
        const int st = kt & 1;
        if (kt < D_ / BK - 1) {
            const float* ap = Ag + (size_t)lrow * D_ + (kt + 1) * BK + kq0;
            const float* bp = Bg + (size_t)lrow * D_ + (kt + 1) * BK + kq0;
            rA[0] = *(const float4*)ap;
            rA[1] = *(const float4*)(ap + 64 * D_);
            rB[0] = *(const float4*)bp;
            rB[1] = *(const float4*)(bp + 64 * D_);
        }

        #pragma unroll
        for (int ks = 0; ks < 2; ks++) {
            const int k0 = ks * 8;
            uint32_t af[4][4], bf[4][2];
            #pragma unroll
            for (int mi = 0; mi < 4; mi++) {
                int row = warp_m + mi * 16 + lr;
                af[mi][0] = sA[st][k0 + lc    ][row];
                af[mi][1] = sA[st][k0 + lc    ][row + 8];
                af[mi][2] = sA[st][k0 + 4 + lc][row];
                af[mi][3] = sA[st][k0 + 4 + lc][row + 8];
            }
            #pragma unroll
            for (int ni = 0; ni < 4; ni++) {
                int col = warp_n + ni * 8 + lr;
                bf[ni][0] = sB[st][k0 + lc    ][col];
                bf[ni][1] = sB[st][k0 + 4 + lc][col];
            }
            #pragma unroll
            for (int mi = 0; mi < 4; mi++)
                #pragma unroll
                for (int ni = 0; ni < 4; ni++)
                    mma_tf32(acc[mi][ni], af[mi], bf[ni]);
        }

        if (kt < D_ / BK - 1) {
            __syncthreads();
            const int ns = 1 - st;
            #pragma unroll
            for (int hf = 0; hf < 2; hf++) {
                int row = lrow + hf * 64;
                sA[ns][kq0+0][row] = f2tf(hf ? rA[1].x : rA[0].x);
                sA[ns][kq0+1][row] = f2tf(hf ? rA[1].y : rA[0].y);
                sA[ns][kq0+2][row] = f2tf(hf ? rA[1].z : rA[0].z);
                sA[ns][kq0+3][row] = f2tf(hf ? rA[1].w : rA[0].w);
                sB[ns][kq0+0][row] = f2tf(hf ? rB[1].x : rB[0].x);
                sB[ns][kq0+1][row] = f2tf(hf ? rB[1].y : rB[0].y);
                sB[ns][kq0+2][row] = f2tf(hf ? rB[1].z : rB[0].z);
                sB[ns][kq0+3][row] = f2tf(hf ? rB[1].w : rB[0].w);
            }
            __syncthreads();
        }
    }

    // epilogue: C fragment layout m16n8: (c0,c1)@(row, 2*lc), (c2,c3)@(row+8, 2*lc)
    float* Og = out + ((size_t)h * N_ + n0) * T_ + t0;
    #pragma unroll
    for (int mi = 0; mi < 4; mi++) {
        int row = warp_m + mi * 16 + lr;
        #pragma unroll
        for (int ni = 0; ni < 4; ni++) {
            int col = warp_n + ni * 8 + 2 * lc;
            float2 v0 = make_float2(acc[mi][ni][0], acc[mi][ni][1]);
            float2 v1 = make_float2(acc[mi][ni][2], acc[mi][ni][3]);
            *(float2*)(Og + (size_t)row * T_ + col)       = v0;
            *(float2*)(Og + (size_t)(row + 8) * T_ + col) = v1;
        }
    }
}

// ---------------------------------------------------------------------------
extern "C" void kernel_launch(void* const* d_in, const int* in_sizes, int n_in,
                              void* d_out, int out_size)
{
    const float* q  = (const float*)d_in[0];
    const float* ko = (const float*)d_in[1];
    const float* kq = (const float*)d_in[2];
    const float* G  = (const float*)d_in[3];
    float* out = (float*)d_out;

    const size_t smem_prep = (128 * SG_S + 64 * SGT_S + 128 * SE_S) * sizeof(float);
    cudaFuncSetAttribute(qjl_prep_kernel, cudaFuncAttributeMaxDynamicSharedMemorySize,
                         (int)smem_prep);

    qjl_prep_kernel<<<dim3(T_ / 64, H_), 256, smem_prep>>>(ko, kq, G);
    qjl_gemm_kernel<<<dim3(T_ / 128, N_ / 128, H_), 256>>>(q, out);
}

// round 3
// speedup vs baseline: 1.7251x; 1.7251x over previous
#include <cuda_runtime.h>
#include <cstdint>

#define H_  32
#define N_  2048
#define T_  2048
#define D_  128
#define R_  64

// scratch: effective K (k_quant + JL sign correction), 32*2048*128 fp32 = 33.5 MB
__device__ float g_keff[H_ * T_ * D_];

// ---------------------------------------------------------------------------
// Prep kernel: per head, per 64-token chunk:
//   s[t,r]    = sign( sum_d (k_orig-k_quant)[t,d] * G[d,r] )     (exact fp32!)
//   keff[t,d] = k_quant[t,d] + (1/64) * sum_r G[d,r] * s[t,r]
// ---------------------------------------------------------------------------
#define SG_S  68
#define SGT_S 132
#define SE_S  65
#define SS_S  68

__global__ void qjl_prep_kernel(const float* __restrict__ k_orig,
                                const float* __restrict__ k_quant,
                                const float* __restrict__ G)
{
    extern __shared__ float sm[];
    float* sG  = sm;
    float* sGT = sG + 128 * SG_S;
    float* sE  = sGT + 64 * SGT_S;
    float* sS  = sE;

    const int tid = threadIdx.x;
    const int h   = blockIdx.y;
    const int t0  = blockIdx.x * 64;

    for (int i = tid; i < D_ * R_; i += 256) {
        int d = i >> 6, r = i & 63;
        float g = G[i];
        sG [d * SG_S  + r] = g;
        sGT[r * SGT_S + d] = g;
    }
    const float* ko = k_orig  + ((size_t)h * T_ + t0) * D_;
    const float* kq = k_quant + ((size_t)h * T_ + t0) * D_;
    for (int i = tid; i < 64 * D_; i += 256) {
        int t = i >> 7, d = i & 127;
        sE[d * SE_S + t] = ko[t * D_ + d] - kq[t * D_ + d];
    }
    __syncthreads();

    {
        const int tc = tid & 63;
        const int rg = tid >> 6;
        float acc[16];
        #pragma unroll
        for (int i = 0; i < 16; i++) acc[i] = 0.f;
        for (int d = 0; d < D_; d++) {
            float ev = sE[d * SE_S + tc];
            const float4* gp = (const float4*)(sG + d * SG_S + rg * 16);
            #pragma unroll
            for (int v = 0; v < 4; v++) {
                float4 g4 = gp[v];
                acc[v*4+0] += ev * g4.x;
                acc[v*4+1] += ev * g4.y;
                acc[v*4+2] += ev * g4.z;
                acc[v*4+3] += ev * g4.w;
            }
        }
        __syncthreads();
        #pragma unroll
        for (int i = 0; i < 16; i++) {
            float s = (acc[i] > 0.f) ? 1.f : ((acc[i] < 0.f) ? -1.f : 0.f);
            sS[(rg * 16 + i) * SS_S + tc] = s;
        }
    }
    __syncthreads();

    {
        const int d   = tid & 127;
        const int tcg = tid >> 7;
        float acc[32];
        #pragma unroll
        for (int j = 0; j < 32; j++) acc[j] = 0.f;
        for (int r = 0; r < R_; r++) {
            float gv = sGT[r * SGT_S + d];
            const float4* sp = (const float4*)(sS + r * SS_S + tcg * 32);
            #pragma unroll
            for (int v = 0; v < 8; v++) {
                float4 s4 = sp[v];
                acc[v*4+0] += gv * s4.x;
                acc[v*4+1] += gv * s4.y;
                acc[v*4+2] += gv * s4.z;
                acc[v*4+3] += gv * s4.w;
            }
        }
        float* ke = g_keff + ((size_t)h * T_ + t0) * D_;
        const float scale = 1.f / 64.f;
        #pragma unroll
        for (int j = 0; j < 32; j++) {
            int t = tcg * 32 + j;
            ke[t * D_ + d] = kq[t * D_ + d] + acc[j] * scale;
        }
    }
}

// ---------------------------------------------------------------------------
// Main GEMM: out[h,n,t] = sum_d q[h,n,d]*keff[h,t,d]  (tf32 mma.sync)
// Block 128x128, BK=16, 256 threads, warp tile 64x32.
// smem layout sX[row][k'] with k' = (k&3)*4 + (k>>2), row stride 20 words:
//   -> each thread's fragment regs for BOTH k-octets are one LDS.128
//   -> STS.32 stores hit all 32 banks exactly once (conflict-free)
// ---------------------------------------------------------------------------
#define BK  16
#define SAS 20          // words per row (16 + 4 pad)

__device__ __forceinline__ uint32_t f2tf(float x) {
    uint32_t y;
    asm("cvt.rna.tf32.f32 %0, %1;" : "=r"(y) : "f"(x));
    return y;
}

__device__ __forceinline__ void mma_tf32(float* c,
                                         uint32_t a0, uint32_t a1, uint32_t a2, uint32_t a3,
                                         uint32_t b0, uint32_t b1) {
    asm volatile(
        "mma.sync.aligned.m16n8k8.row.col.f32.tf32.tf32.f32 "
        "{%0,%1,%2,%3}, {%4,%5,%6,%7}, {%8,%9}, {%0,%1,%2,%3};\n"
        : "+f"(c[0]), "+f"(c[1]), "+f"(c[2]), "+f"(c[3])
        : "r"(a0), "r"(a1), "r"(a2), "r"(a3), "r"(b0), "r"(b1));
}

__global__ __launch_bounds__(256, 2) void qjl_gemm_kernel(const float* __restrict__ q,
                                                          float* __restrict__ out)
{
    __shared__ __align__(16) uint32_t sA[2][128 * SAS];
    __shared__ __align__(16) uint32_t sB[2][128 * SAS];

    const int tid  = threadIdx.x;
    const int warp = tid >> 5;
    const int lane = tid & 31;
    const int h  = blockIdx.z;
    const int n0 = blockIdx.y * 128;
    const int t0 = blockIdx.x * 128;

    const float* Ag = q      + ((size_t)h * N_ + n0) * D_;
    const float* Bg = g_keff + ((size_t)h * T_ + t0) * D_;

    // loader: thread -> (row = tid>>2 and row+64, q4 = tid&3 -> k base q4*4)
    const int lrow = tid >> 2;
    const int q4   = tid & 3;

    const int warp_m = (warp & 1) * 64;
    const int warp_n = (warp >> 1) * 32;
    const int lr = lane >> 2;
    const int lc = lane & 3;

    float acc[4][4][4];
    #pragma unroll
    for (int mi = 0; mi < 4; mi++)
        #pragma unroll
        for (int ni = 0; ni < 4; ni++)
            #pragma unroll
            for (int v = 0; v < 4; v++) acc[mi][ni][v] = 0.f;

    float4 ra0, ra1, rb0, rb1;

    // prologue: LDG chunk 0
    {
        const float* ap = Ag + (size_t)lrow * D_ + q4 * 4;
        const float* bp = Bg + (size_t)lrow * D_ + q4 * 4;
        ra0 = *(const float4*)ap;
        ra1 = *(const float4*)(ap + 64 * D_);
        rb0 = *(const float4*)bp;
        rb1 = *(const float4*)(bp + 64 * D_);
    }
    // store stage 0:  value (row, k=q4*4+comp) -> word row*SAS + comp*4 + q4
    {
        uint32_t* a0p = &sA[0][lrow * SAS + q4];
        uint32_t* a1p = &sA[0][(lrow + 64) * SAS + q4];
        uint32_t* b0p = &sB[0][lrow * SAS + q4];
        uint32_t* b1p = &sB[0][(lrow + 64) * SAS + q4];
        a0p[0] = f2tf(ra0.x); a0p[4] = f2tf(ra0.y); a0p[8] = f2tf(ra0.z); a0p[12] = f2tf(ra0.w);
        a1p[0] = f2tf(ra1.x); a1p[4] = f2tf(ra1.y); a1p[8] = f2tf(ra1.z); a1p[12] = f2tf(ra1.w);
        b0p[0] = f2tf(rb0.x); b0p[4] = f2tf(rb0.y); b0p[8] = f2tf(rb0.z); b0p[12] = f2tf(rb0.w);
        b1p[0] = f2tf(rb1.x); b1p[4] = f2tf(rb1.y); b1p[8] = f2tf(rb1.z); b1p[12] = f2tf(rb1.w);
    }
    __syncthreads();

    #pragma unroll 1
    for (int kt = 0; kt < D_ / BK; kt++) {
        const int st = kt & 1;

        // B fragments: one LDS.128 per ni covers both k-octets
        uint4 bf[4];
        #pragma unroll
        for (int ni = 0; ni < 4; ni++)
            bf[ni] = *(const uint4*)&sB[st][(warp_n + ni * 8 + lr) * SAS + lc * 4];

        // A fragments, half 0 (mi = 0,1)
        uint4 alo[2], ahi[2];
        #pragma unroll
        for (int mi = 0; mi < 2; mi++) {
            int row = warp_m + mi * 16 + lr;
            alo[mi] = *(const uint4*)&sA[st][row * SAS + lc * 4];
            ahi[mi] = *(const uint4*)&sA[st][(row + 8) * SAS + lc * 4];
        }

        // prefetch next gmem chunk (latency hides under the MMA block)
        if (kt < D_ / BK - 1) {
            const float* ap = Ag + (size_t)lrow * D_ + (kt + 1) * BK + q4 * 4;
            const float* bp = Bg + (size_t)lrow * D_ + (kt + 1) * BK + q4 * 4;
            ra0 = *(const float4*)ap;
            ra1 = *(const float4*)(ap + 64 * D_);
            rb0 = *(const float4*)bp;
            rb1 = *(const float4*)(bp + 64 * D_);
        }

        // MMA half 0
        #pragma unroll
        for (int mi = 0; mi < 2; mi++)
            #pragma unroll
            for (int ni = 0; ni < 4; ni++) {
                mma_tf32(acc[mi][ni], alo[mi].x, ahi[mi].x, alo[mi].y, ahi[mi].y,
                         bf[ni].x, bf[ni].y);
                mma_tf32(acc[mi][ni], alo[mi].z, ahi[mi].z, alo[mi].w, ahi[mi].w,
                         bf[ni].z, bf[ni].w);
            }

        // A fragments, half 1 (mi = 2,3)
        #pragma unroll
        for (int mi = 0; mi < 2; mi++) {
            int row = warp_m + (mi + 2) * 16 + lr;
            alo[mi] = *(const uint4*)&sA[st][row * SAS + lc * 4];
            ahi[mi] = *(const uint4*)&sA[st][(row + 8) * SAS + lc * 4];
        }
        #pragma unroll
        for (int mi = 0; mi < 2; mi++)
            #pragma unroll
            for (int ni = 0; ni < 4; ni++) {
                mma_tf32(acc[mi + 2][ni], alo[mi].x, ahi[mi].x, alo[mi].y, ahi[mi].y,
                         bf[ni].x, bf[ni].y);
                mma_tf32(acc[mi + 2][ni], alo[mi].z, ahi[mi].z, alo[mi].w, ahi[mi].w,
                         bf[ni].z, bf[ni].w);
            }

        // store next chunk into the other stage (readers of `st` unaffected)
        if (kt < D_ / BK - 1) {
            const int ns = 1 - st;
            uint32_t* a0p = &sA[ns][lrow * SAS + q4];
            uint32_t* a1p = &sA[ns][(lrow + 64) * SAS + q4];
            uint32_t* b0p = &sB[ns][lrow * SAS + q4];
            uint32_t* b1p = &sB[ns][(lrow + 64) * SAS + q4];
            a0p[0] = f2tf(ra0.x); a0p[4] = f2tf(ra0.y); a0p[8] = f2tf(ra0.z); a0p[12] = f2tf(ra0.w);
            a1p[0] = f2tf(ra1.x); a1p[4] = f2tf(ra1.y); a1p[8] = f2tf(ra1.z); a1p[12] = f2tf(ra1.w);
            b0p[0] = f2tf(rb0.x); b0p[4] = f2tf(rb0.y); b0p[8] = f2tf(rb0.z); b0p[12] = f2tf(rb0.w);
            b1p[0] = f2tf(rb1.x); b1p[4] = f2tf(rb1.y); b1p[8] = f2tf(rb1.z); b1p[12] = f2tf(rb1.w);
        }
        __syncthreads();
    }

    // epilogue: C fragment layout m16n8: (c0,c1)@(row, 2*lc), (c2,c3)@(row+8, 2*lc)
    float* Og = out + ((size_t)h * N_ + n0) * T_ + t0;
    #pragma unroll
    for (int mi = 0; mi < 4; mi++) {
        int row = warp_m + mi * 16 + lr;
        #pragma unroll
        for (int ni = 0; ni < 4; ni++) {
            int col = warp_n + ni * 8 + 2 * lc;
            float2 v0 = make_float2(acc[mi][ni][0], acc[mi][ni][1]);
            float2 v1 = make_float2(acc[mi][ni][2], acc[mi][ni][3]);
            *(float2*)(Og + (size_t)row * T_ + col)       = v0;
            *(float2*)(Og + (size_t)(row + 8) * T_ + col) = v1;
        }
    }
}

// ---------------------------------------------------------------------------
extern "C" void kernel_launch(void* const* d_in, const int* in_sizes, int n_in,
                              void* d_out, int out_size)
{
    const float* q  = (const float*)d_in[0];
    const float* ko = (const float*)d_in[1];
    const float* kq = (const float*)d_in[2];
    const float* G  = (const float*)d_in[3];
    float* out = (float*)d_out;

    const size_t smem_prep = (128 * SG_S + 64 * SGT_S + 128 * SE_S) * sizeof(float);
    cudaFuncSetAttribute(qjl_prep_kernel, cudaFuncAttributeMaxDynamicSharedMemorySize,
                         (int)smem_prep);

    qjl_prep_kernel<<<dim3(T_ / 64, H_), 256, smem_prep>>>(ko, kq, G);
    qjl_gemm_kernel<<<dim3(T_ / 128, N_ / 128, H_), 256>>>(q, out);
}

// round 4
// speedup vs baseline: 2.4970x; 1.4475x over previous
#include <cuda_runtime.h>
#include <cuda_fp16.h>
#include <cstdint>

#define H_  32
#define N_  2048
#define T_  2048
#define D_  128
#define R_  64

// fp16 staging buffers
__device__ __align__(16) __half g_keffh[H_ * T_ * D_];   // 16.8 MB
__device__ __align__(16) __half g_qh  [H_ * N_ * D_];    // 16.8 MB

// ---------------------------------------------------------------------------
// q -> fp16 conversion (RNE), 8 floats per thread
// ---------------------------------------------------------------------------
__global__ void qcvt_kernel(const float* __restrict__ q)
{
    int i = blockIdx.x * blockDim.x + threadIdx.x;     // one per 8 elems
    const float4* src = (const float4*)q + (size_t)i * 2;
    float4 f0 = src[0], f1 = src[1];
    union { __half2 h[4]; uint4 u; } pk;
    pk.h[0] = __floats2half2_rn(f0.x, f0.y);
    pk.h[1] = __floats2half2_rn(f0.z, f0.w);
    pk.h[2] = __floats2half2_rn(f1.x, f1.y);
    pk.h[3] = __floats2half2_rn(f1.z, f1.w);
    ((uint4*)g_qh)[i] = pk.u;
}

// ---------------------------------------------------------------------------
// Prep kernel: per head, per 64-token chunk (exact fp32 math):
//   s[t,r]    = sign( sum_d (k_orig-k_quant)[t,d] * G[d,r] )
//   keff[t,d] = fp16( k_quant[t,d] + (1/64) * sum_r G[d,r] * s[t,r] )
// ---------------------------------------------------------------------------
#define SG_S  68
#define SGT_S 132
#define SE_S  65
#define SS_S  68

__global__ void qjl_prep_kernel(const float* __restrict__ k_orig,
                                const float* __restrict__ k_quant,
                                const float* __restrict__ G)
{
    extern __shared__ float sm[];
    float* sG  = sm;
    float* sGT = sG + 128 * SG_S;
    float* sE  = sGT + 64 * SGT_S;
    float* sS  = sE;

    const int tid = threadIdx.x;
    const int h   = blockIdx.y;
    const int t0  = blockIdx.x * 64;

    for (int i = tid; i < D_ * R_; i += 256) {
        int d = i >> 6, r = i & 63;
        float g = G[i];
        sG [d * SG_S  + r] = g;
        sGT[r * SGT_S + d] = g;
    }
    const float* ko = k_orig  + ((size_t)h * T_ + t0) * D_;
    const float* kq = k_quant + ((size_t)h * T_ + t0) * D_;
    for (int i = tid; i < 64 * D_; i += 256) {
        int t = i >> 7, d = i & 127;
        sE[d * SE_S + t] = ko[t * D_ + d] - kq[t * D_ + d];
    }
    __syncthreads();

    {
        const int tc = tid & 63;
        const int rg = tid >> 6;
        float acc[16];
        #pragma unroll
        for (int i = 0; i < 16; i++) acc[i] = 0.f;
        for (int d = 0; d < D_; d++) {
            float ev = sE[d * SE_S + tc];
            const float4* gp = (const float4*)(sG + d * SG_S + rg * 16);
            #pragma unroll
            for (int v = 0; v < 4; v++) {
                float4 g4 = gp[v];
                acc[v*4+0] += ev * g4.x;
                acc[v*4+1] += ev * g4.y;
                acc[v*4+2] += ev * g4.z;
                acc[v*4+3] += ev * g4.w;
            }
        }
        __syncthreads();
        #pragma unroll
        for (int i = 0; i < 16; i++) {
            float s = (acc[i] > 0.f) ? 1.f : ((acc[i] < 0.f) ? -1.f : 0.f);
            sS[(rg * 16 + i) * SS_S + tc] = s;
        }
    }
    __syncthreads();

    {
        const int d   = tid & 127;
        const int tcg = tid >> 7;
        float acc[32];
        #pragma unroll
        for (int j = 0; j < 32; j++) acc[j] = 0.f;
        for (int r = 0; r < R_; r++) {
            float gv = sGT[r * SGT_S + d];
            const float4* sp = (const float4*)(sS + r * SS_S + tcg * 32);
            #pragma unroll
            for (int v = 0; v < 8; v++) {
                float4 s4 = sp[v];
                acc[v*4+0] += gv * s4.x;
                acc[v*4+1] += gv * s4.y;
                acc[v*4+2] += gv * s4.z;
                acc[v*4+3] += gv * s4.w;
            }
        }
        __half* ke = g_keffh + ((size_t)h * T_ + t0) * D_;
        const float scale = 1.f / 64.f;
        #pragma unroll
        for (int j = 0; j < 32; j++) {
            int t = tcg * 32 + j;
            ke[t * D_ + d] = __float2half_rn(kq[t * D_ + d] + acc[j] * scale);
        }
    }
}

// ---------------------------------------------------------------------------
// Main GEMM: out[h,n,t] = sum_d qh[h,n,d]*keffh[h,t,d]  (fp16 mma, fp32 acc)
// Block 128x128, BK=32 halves (16 b32 words/row), 256 threads, warp 64x32.
// smem: stride 16 words (64B rows), 16B-granule swizzle g' = g ^ ((row>>1)&3).
//   word w (k-pair) of row stored at: row*16 + ((w&3) ^ ((row>>1)&3))*4 + (w>>2)
//   -> LDS.128 fragment loads conflict-free (quarter-warp residues distinct)
//   -> STS.32 stores conflict-free (all 32 banks hit once per instruction)
// ---------------------------------------------------------------------------
#define NKT 4      // 128 / 32

__device__ __forceinline__ void mma_f16(float* c,
                                        uint32_t a0, uint32_t a1, uint32_t a2, uint32_t a3,
                                        uint32_t b0, uint32_t b1) {
    asm volatile(
        "mma.sync.aligned.m16n8k16.row.col.f32.f16.f16.f32 "
        "{%0,%1,%2,%3}, {%4,%5,%6,%7}, {%8,%9}, {%0,%1,%2,%3};\n"
        : "+f"(c[0]), "+f"(c[1]), "+f"(c[2]), "+f"(c[3])
        : "r"(a0), "r"(a1), "r"(a2), "r"(a3), "r"(b0), "r"(b1));
}

__global__ __launch_bounds__(256, 2) void qjl_gemm_kernel(float* __restrict__ out)
{
    __shared__ __align__(16) uint32_t sA[2][128 * 16];
    __shared__ __align__(16) uint32_t sB[2][128 * 16];

    const int tid  = threadIdx.x;
    const int warp = tid >> 5;
    const int lane = tid & 31;
    const int h  = blockIdx.z;
    const int n0 = blockIdx.y * 128;
    const int t0 = blockIdx.x * 128;

    const __half* Ag = g_qh   + ((size_t)h * N_ + n0) * D_;
    const __half* Bg = g_keffh + ((size_t)h * T_ + t0) * D_;

    // loader: thread -> rows lrow, lrow+64; q4 selects 16B (4 words) of the chunk
    const int lrow = tid >> 2;
    const int q4   = tid & 3;

    const int warp_m = (warp & 1) * 64;
    const int warp_n = (warp >> 1) * 32;
    const int lr = lane >> 2;   // group id (row within tile)
    const int lc = lane & 3;    // k-word id

    float acc[4][4][4];
    #pragma unroll
    for (int mi = 0; mi < 4; mi++)
        #pragma unroll
        for (int ni = 0; ni < 4; ni++)
            #pragma unroll
            for (int v = 0; v < 4; v++) acc[mi][ni][v] = 0.f;

    // swizzled store of one 16B gmem chunk (4 words w = q4*4 + j, j=0..3)
    const int rs0  = (lrow >> 1) & 3;          // rows lrow and lrow+64: +64 -> (>>1)+32, &3 same
    uint4 ra0, ra1, rb0, rb1;

#define STORE_CH(arr, st, row, rs, v)                                     \
    {                                                                     \
        uint32_t* p_ = &arr[st][(row) * 16 + q4];                         \
        p_[((0 ^ (rs)) << 2)] = (v).x;                                    \
        p_[((1 ^ (rs)) << 2)] = (v).y;                                    \
        p_[((2 ^ (rs)) << 2)] = (v).z;                                    \
        p_[((3 ^ (rs)) << 2)] = (v).w;                                    \
    }

    // prologue: LDG chunk 0  (chunk kt = uint4 index kt*4 + q4 within row)
    {
        const uint4* ap = (const uint4*)(Ag + (size_t)lrow * D_);
        const uint4* bp = (const uint4*)(Bg + (size_t)lrow * D_);
        ra0 = ap[q4];
        ra1 = ap[64 * (D_ / 8) + q4];
        rb0 = bp[q4];
        rb1 = bp[64 * (D_ / 8) + q4];
    }
    STORE_CH(sA, 0, lrow,      rs0, ra0);
    STORE_CH(sA, 0, lrow + 64, rs0, ra1);
    STORE_CH(sB, 0, lrow,      rs0, rb0);
    STORE_CH(sB, 0, lrow + 64, rs0, rb1);
    __syncthreads();

    #pragma unroll
    for (int kt = 0; kt < NKT; kt++) {
        const int st = kt & 1;

        // B fragments: one LDS.128 per ni covers both k8-steps
        uint4 bf[4];
        #pragma unroll
        for (int ni = 0; ni < 4; ni++) {
            int row = warp_n + ni * 8 + lr;
            int g   = (lc ^ ((row >> 1) & 3)) << 2;
            bf[ni] = *(const uint4*)&sB[st][row * 16 + g];
        }

        // A fragments half 0 (mi = 0,1); (row+8)>>1 differs by 4 -> same swizzle
        uint4 alo[2], ahi[2];
        #pragma unroll
        for (int mi = 0; mi < 2; mi++) {
            int row = warp_m + mi * 16 + lr;
            int g   = (lc ^ ((row >> 1) & 3)) << 2;
            alo[mi] = *(const uint4*)&sA[st][row * 16 + g];
            ahi[mi] = *(const uint4*)&sA[st][(row + 8) * 16 + g];
        }

        // prefetch next gmem chunk (latency hides under the MMA block)
        if (kt < NKT - 1) {
            const uint4* ap = (const uint4*)(Ag + (size_t)lrow * D_);
            const uint4* bp = (const uint4*)(Bg + (size_t)lrow * D_);
            ra0 = ap[(kt + 1) * 4 + q4];
            ra1 = ap[64 * (D_ / 8) + (kt + 1) * 4 + q4];
            rb0 = bp[(kt + 1) * 4 + q4];
            rb1 = bp[64 * (D_ / 8) + (kt + 1) * 4 + q4];
        }

        // MMA half 0:  uint4 = (f(s0), f'(s0), f(s1), f'(s1))
        #pragma unroll
        for (int mi = 0; mi < 2; mi++)
            #pragma unroll
            for (int ni = 0; ni < 4; ni++) {
                mma_f16(acc[mi][ni], alo[mi].x, ahi[mi].x, alo[mi].y, ahi[mi].y,
                        bf[ni].x, bf[ni].y);
                mma_f16(acc[mi][ni], alo[mi].z, ahi[mi].z, alo[mi].w, ahi[mi].w,
                        bf[ni].z, bf[ni].w);
            }

        // A fragments half 1 (mi = 2,3)
        #pragma unroll
        for (int mi = 0; mi < 2; mi++) {
            int row = warp_m + (mi + 2) * 16 + lr;
            int g   = (lc ^ ((row >> 1) & 3)) << 2;
            alo[mi] = *(const uint4*)&sA[st][row * 16 + g];
            ahi[mi] = *(const uint4*)&sA[st][(row + 8) * 16 + g];
        }
        #pragma unroll
        for (int mi = 0; mi < 2; mi++)
            #pragma unroll
            for (int ni = 0; ni < 4; ni++) {
                mma_f16(acc[mi + 2][ni], alo[mi].x, ahi[mi].x, alo[mi].y, ahi[mi].y,
                        bf[ni].x, bf[ni].y);
                mma_f16(acc[mi + 2][ni], alo[mi].z, ahi[mi].z, alo[mi].w, ahi[mi].w,
                        bf[ni].z, bf[ni].w);
            }

        if (kt < NKT - 1) {
            const int ns = 1 - st;
            STORE_CH(sA, ns, lrow,      rs0, ra0);
            STORE_CH(sA, ns, lrow + 64, rs0, ra1);
            STORE_CH(sB, ns, lrow,      rs0, rb0);
            STORE_CH(sB, ns, lrow + 64, rs0, rb1);
        }
        __syncthreads();
    }

    // epilogue: C fragment m16n8: (c0,c1)@(row, 2*lc), (c2,c3)@(row+8, 2*lc)
    float* Og = out + ((size_t)h * N_ + n0) * T_ + t0;
    #pragma unroll
    for (int mi = 0; mi < 4; mi++) {
        int row = warp_m + mi * 16 + lr;
        #pragma unroll
        for (int ni = 0; ni < 4; ni++) {
            int col = warp_n + ni * 8 + 2 * lc;
            float2 v0 = make_float2(acc[mi][ni][0], acc[mi][ni][1]);
            float2 v1 = make_float2(acc[mi][ni][2], acc[mi][ni][3]);
            *(float2*)(Og + (size_t)row * T_ + col)       = v0;
            *(float2*)(Og + (size_t)(row + 8) * T_ + col) = v1;
        }
    }
#undef STORE_CH
}

// ---------------------------------------------------------------------------
extern "C" void kernel_launch(void* const* d_in, const int* in_sizes, int n_in,
                              void* d_out, int out_size)
{
    const float* q  = (const float*)d_in[0];
    const float* ko = (const float*)d_in[1];
    const float* kq = (const float*)d_in[2];
    const float* G  = (const float*)d_in[3];
    float* out = (float*)d_out;

    const size_t smem_prep = (128 * SG_S + 64 * SGT_S + 128 * SE_S) * sizeof(float);
    cudaFuncSetAttribute(qjl_prep_kernel, cudaFuncAttributeMaxDynamicSharedMemorySize,
                         (int)smem_prep);

    qcvt_kernel<<<(H_ * N_ * D_) / (256 * 8), 256>>>(q);
    qjl_prep_kernel<<<dim3(T_ / 64, H_), 256, smem_prep>>>(ko, kq, G);
    qjl_gemm_kernel<<<dim3(T_ / 128, N_ / 128, H_), 256>>>(out);
}

// round 5
// speedup vs baseline: 2.7221x; 1.0902x over previous
#include <cuda_runtime.h>
#include <cuda_fp16.h>
#include <cstdint>

#define H_  32
#define N_  2048
#define T_  2048
#define D_  128
#define R_  64

// fp16 staging buffers
__device__ __align__(16) __half g_keffh[H_ * T_ * D_];   // 16.8 MB
__device__ __align__(16) __half g_qh  [H_ * N_ * D_];    // 16.8 MB

// ---------------------------------------------------------------------------
// packed f32x2 helpers (Blackwell sm_100+ family, NOT 'a'-gated)
// ---------------------------------------------------------------------------
__device__ __forceinline__ uint64_t pack2(float lo, float hi) {
    uint64_t v; asm("mov.b64 %0, {%1, %2};" : "=l"(v) : "f"(lo), "f"(hi)); return v;
}
__device__ __forceinline__ void unpack2(uint64_t v, float& lo, float& hi) {
    asm("mov.b64 {%0, %1}, %2;" : "=f"(lo), "=f"(hi) : "l"(v));
}
__device__ __forceinline__ uint64_t ffma2(uint64_t a, uint64_t b, uint64_t c) {
    uint64_t d;
    asm("fma.rn.f32x2 %0, %1, %2, %3;" : "=l"(d) : "l"(a), "l"(b), "l"(c));
    return d;
}

// ---------------------------------------------------------------------------
// q -> fp16 conversion (RNE), 8 floats per thread
// ---------------------------------------------------------------------------
__global__ void qcvt_kernel(const float* __restrict__ q)
{
    int i = blockIdx.x * blockDim.x + threadIdx.x;     // one per 8 elems
    const float4* src = (const float4*)q + (size_t)i * 2;
    float4 f0 = src[0], f1 = src[1];
    union { __half2 h[4]; uint4 u; } pk;
    pk.h[0] = __floats2half2_rn(f0.x, f0.y);
    pk.h[1] = __floats2half2_rn(f0.z, f0.w);
    pk.h[2] = __floats2half2_rn(f1.x, f1.y);
    pk.h[3] = __floats2half2_rn(f1.z, f1.w);
    ((uint4*)g_qh)[i] = pk.u;
}

// ---------------------------------------------------------------------------
// Prep kernel: per head, per 64-token chunk (exact fp32 math, f32x2 packed):
//   s[t,r]    = sign( sum_d (k_orig-k_quant)[t,d] * G[d,r] )
//   keff[t,d] = fp16( k_quant[t,d] + (1/64) * sum_r G[d,r] * s[t,r] )
// ---------------------------------------------------------------------------
#define SG_S  68
#define SGT_S 132
#define SE_S  65
#define SS_S  68

__global__ void qjl_prep_kernel(const float* __restrict__ k_orig,
                                const float* __restrict__ k_quant,
                                const float* __restrict__ G)
{
    extern __shared__ float sm[];
    float* sG  = sm;                       // [128][SG_S]  (d, r)
    float* sGT = sG + 128 * SG_S;          // [64][SGT_S]  (r, d)
    float* sE  = sGT + 64 * SGT_S;         // [128][SE_S]  (d, t)
    float* sS  = sE;                       // [64][SS_S]   (r, t)  aliases sE

    const int tid = threadIdx.x;
    const int h   = blockIdx.y;
    const int t0  = blockIdx.x * 64;

    for (int i = tid; i < D_ * R_; i += 256) {
        int d = i >> 6, r = i & 63;
        float g = G[i];
        sG [d * SG_S  + r] = g;
        sGT[r * SGT_S + d] = g;
    }
    const float* ko = k_orig  + ((size_t)h * T_ + t0) * D_;
    const float* kq = k_quant + ((size_t)h * T_ + t0) * D_;
    for (int i = tid; i < 64 * D_; i += 256) {
        int t = i >> 7, d = i & 127;
        sE[d * SE_S + t] = ko[t * D_ + d] - kq[t * D_ + d];
    }
    __syncthreads();

    // ---- stage 1: s = sign(e @ G); thread = (tc, rg), 16 r's as 8 f32x2 pairs
    {
        const int tc = tid & 63;
        const int rg = tid >> 6;
        uint64_t acc[8];
        #pragma unroll
        for (int i = 0; i < 8; i++) acc[i] = pack2(0.f, 0.f);
        for (int d = 0; d < D_; d++) {
            float ev = sE[d * SE_S + tc];
            uint64_t ev2 = pack2(ev, ev);
            const ulonglong2* gp = (const ulonglong2*)(sG + d * SG_S + rg * 16);
            #pragma unroll
            for (int v = 0; v < 4; v++) {
                ulonglong2 g2 = gp[v];
                acc[v*2+0] = ffma2(ev2, g2.x, acc[v*2+0]);
                acc[v*2+1] = ffma2(ev2, g2.y, acc[v*2+1]);
            }
        }
        __syncthreads();   // all sE reads done before sS (alias) writes
        #pragma unroll
        for (int i = 0; i < 8; i++) {
            float a0, a1;
            unpack2(acc[i], a0, a1);
            float s0 = (a0 > 0.f) ? 1.f : ((a0 < 0.f) ? -1.f : 0.f);
            float s1 = (a1 > 0.f) ? 1.f : ((a1 < 0.f) ? -1.f : 0.f);
            sS[(rg * 16 + 2*i    ) * SS_S + tc] = s0;
            sS[(rg * 16 + 2*i + 1) * SS_S + tc] = s1;
        }
    }
    __syncthreads();

    // ---- stage 2: keff = fp16(kq + (G @ s^T)/64); thread = (d, tcg), 32 t's
    {
        const int d   = tid & 127;
        const int tcg = tid >> 7;
        uint64_t acc[16];
        #pragma unroll
        for (int j = 0; j < 16; j++) acc[j] = pack2(0.f, 0.f);
        for (int r = 0; r < R_; r++) {
            float gv = sGT[r * SGT_S + d];
            uint64_t gv2 = pack2(gv, gv);
            const ulonglong2* sp = (const ulonglong2*)(sS + r * SS_S + tcg * 32);
            #pragma unroll
            for (int v = 0; v < 8; v++) {
                ulonglong2 s2 = sp[v];
                acc[v*2+0] = ffma2(gv2, s2.x, acc[v*2+0]);
                acc[v*2+1] = ffma2(gv2, s2.y, acc[v*2+1]);
            }
        }
        __half* ke = g_keffh + ((size_t)h * T_ + t0) * D_;
        const float scale = 1.f / 64.f;
        #pragma unroll
        for (int j = 0; j < 16; j++) {
            float a0, a1;
            unpack2(acc[j], a0, a1);
            int t0j = tcg * 32 + 2*j;
            ke[(t0j    ) * D_ + d] = __float2half_rn(kq[(t0j    ) * D_ + d] + a0 * scale);
            ke[(t0j + 1) * D_ + d] = __float2half_rn(kq[(t0j + 1) * D_ + d] + a1 * scale);
        }
    }
}

// ---------------------------------------------------------------------------
// Main GEMM: out[h,n,t] = sum_d qh[h,n,d]*keffh[h,t,d]  (fp16 mma, fp32 acc)
// Block 128x128, 256 threads, warp 64x32. K=128 fully resident in smem:
// 4 chunks of 32 halves each, per-chunk layout identical to the proven R4
// swizzle (row stride 16 words, g' = g ^ ((row>>1)&3) on 16B granules).
// Single __syncthreads; all 4 kt MMA blocks fully independent (max ILP).
// ---------------------------------------------------------------------------
#define NKT 4      // 128 / 32

__device__ __forceinline__ void mma_f16(float* c,
                                        uint32_t a0, uint32_t a1, uint32_t a2, uint32_t a3,
                                        uint32_t b0, uint32_t b1) {
    asm volatile(
        "mma.sync.aligned.m16n8k16.row.col.f32.f16.f16.f32 "
        "{%0,%1,%2,%3}, {%4,%5,%6,%7}, {%8,%9}, {%0,%1,%2,%3};\n"
        : "+f"(c[0]), "+f"(c[1]), "+f"(c[2]), "+f"(c[3])
        : "r"(a0), "r"(a1), "r"(a2), "r"(a3), "r"(b0), "r"(b1));
}

__global__ __launch_bounds__(256, 2) void qjl_gemm_kernel(float* __restrict__ out)
{
    __shared__ __align__(16) uint32_t sA[NKT][128 * 16];
    __shared__ __align__(16) uint32_t sB[NKT][128 * 16];

    const int tid  = threadIdx.x;
    const int warp = tid >> 5;
    const int lane = tid & 31;
    const int h  = blockIdx.z;
    const int n0 = blockIdx.y * 128;
    const int t0 = blockIdx.x * 128;

    const uint4* Ag4 = (const uint4*)(g_qh    + ((size_t)h * N_ + n0) * D_);
    const uint4* Bg4 = (const uint4*)(g_keffh + ((size_t)h * T_ + t0) * D_);

    const int lrow = tid >> 2;          // rows lrow, lrow+64
    const int q4   = tid & 3;           // 16B slot within a 32-half chunk
    const int rs0  = (lrow >> 1) & 3;   // same for lrow+64

#define STORE_CH(arr, row, rs, v)                                         \
    {                                                                     \
        uint32_t* p_ = &arr[(row) * 16 + q4];                             \
        p_[((0 ^ (rs)) << 2)] = (v).x;                                    \
        p_[((1 ^ (rs)) << 2)] = (v).y;                                    \
        p_[((2 ^ (rs)) << 2)] = (v).z;                                    \
        p_[((3 ^ (rs)) << 2)] = (v).w;                                    \
    }

    // load the entire K=128 tile (4 chunks), then one sync
    #pragma unroll
    for (int kt = 0; kt < NKT; kt++) {
        uint4 a0 = Ag4[(size_t)lrow * 16 + kt * 4 + q4];
        uint4 a1 = Ag4[(size_t)(lrow + 64) * 16 + kt * 4 + q4];
        uint4 b0 = Bg4[(size_t)lrow * 16 + kt * 4 + q4];
        uint4 b1 = Bg4[(size_t)(lrow + 64) * 16 + kt * 4 + q4];
        STORE_CH(sA[kt], lrow,      rs0, a0);
        STORE_CH(sA[kt], lrow + 64, rs0, a1);
        STORE_CH(sB[kt], lrow,      rs0, b0);
        STORE_CH(sB[kt], lrow + 64, rs0, b1);
    }
    __syncthreads();

    const int warp_m = (warp & 1) * 64;
    const int warp_n = (warp >> 1) * 32;
    const int lr = lane >> 2;
    const int lc = lane & 3;

    float acc[4][4][4];
    #pragma unroll
    for (int mi = 0; mi < 4; mi++)
        #pragma unroll
        for (int ni = 0; ni < 4; ni++)
            #pragma unroll
            for (int v = 0; v < 4; v++) acc[mi][ni][v] = 0.f;

    #pragma unroll
    for (int kt = 0; kt < NKT; kt++) {
        // B fragments: one LDS.128 per ni covers both k8-steps
        uint4 bf[4];
        #pragma unroll
        for (int ni = 0; ni < 4; ni++) {
            int row = warp_n + ni * 8 + lr;
            int g   = (lc ^ ((row >> 1) & 3)) << 2;
            bf[ni] = *(const uint4*)&sB[kt][row * 16 + g];
        }

        // A fragments half 0 (mi = 0,1)
        uint4 alo[2], ahi[2];
        #pragma unroll
        for (int mi = 0; mi < 2; mi++) {
            int row = warp_m + mi * 16 + lr;
            int g   = (lc ^ ((row >> 1) & 3)) << 2;
            alo[mi] = *(const uint4*)&sA[kt][row * 16 + g];
            ahi[mi] = *(const uint4*)&sA[kt][(row + 8) * 16 + g];
        }
        #pragma unroll
        for (int mi = 0; mi < 2; mi++)
            #pragma unroll
            for (int ni = 0; ni < 4; ni++) {
                mma_f16(acc[mi][ni], alo[mi].x, ahi[mi].x, alo[mi].y, ahi[mi].y,
                        bf[ni].x, bf[ni].y);
                mma_f16(acc[mi][ni], alo[mi].z, ahi[mi].z, alo[mi].w, ahi[mi].w,
                        bf[ni].z, bf[ni].w);
            }

        // A fragments half 1 (mi = 2,3)
        #pragma unroll
        for (int mi = 0; mi < 2; mi++) {
            int row = warp_m + (mi + 2) * 16 + lr;
            int g   = (lc ^ ((row >> 1) & 3)) << 2;
            alo[mi] = *(const uint4*)&sA[kt][row * 16 + g];
            ahi[mi] = *(const uint4*)&sA[kt][(row + 8) * 16 + g];
        }
        #pragma unroll
        for (int mi = 0; mi < 2; mi++)
            #pragma unroll
            for (int ni = 0; ni < 4; ni++) {
                mma_f16(acc[mi + 2][ni], alo[mi].x, ahi[mi].x, alo[mi].y, ahi[mi].y,
                        bf[ni].x, bf[ni].y);
                mma_f16(acc[mi + 2][ni], alo[mi].z, ahi[mi].z, alo[mi].w, ahi[mi].w,
                        bf[ni].z, bf[ni].w);
            }
    }

    // epilogue: C fragment m16n8: (c0,c1)@(row, 2*lc), (c2,c3)@(row+8, 2*lc)
    float* Og = out + ((size_t)h * N_ + n0) * T_ + t0;
    #pragma unroll
    for (int mi = 0; mi < 4; mi++) {
        int row = warp_m + mi * 16 + lr;
        #pragma unroll
        for (int ni = 0; ni < 4; ni++) {
            int col = warp_n + ni * 8 + 2 * lc;
            float2 v0 = make_float2(acc[mi][ni][0], acc[mi][ni][1]);
            float2 v1 = make_float2(acc[mi][ni][2], acc[mi][ni][3]);
            *(float2*)(Og + (size_t)row * T_ + col)       = v0;
            *(float2*)(Og + (size_t)(row + 8) * T_ + col) = v1;
        }
    }
#undef STORE_CH
}

// ---------------------------------------------------------------------------
extern "C" void kernel_launch(void* const* d_in, const int* in_sizes, int n_in,
                              void* d_out, int out_size)
{
    const float* q  = (const float*)d_in[0];
    const float* ko = (const float*)d_in[1];
    const float* kq = (const float*)d_in[2];
    const float* G  = (const float*)d_in[3];
    float* out = (float*)d_out;

    const size_t smem_prep = (128 * SG_S + 64 * SGT_S + 128 * SE_S) * sizeof(float);
    cudaFuncSetAttribute(qjl_prep_kernel, cudaFuncAttributeMaxDynamicSharedMemorySize,
                         (int)smem_prep);

    qcvt_kernel<<<(H_ * N_ * D_) / (256 * 8), 256>>>(q);
    qjl_prep_kernel<<<dim3(T_ / 64, H_), 256, smem_prep>>>(ko, kq, G);
    qjl_gemm_kernel<<<dim3(T_ / 128, N_ / 128, H_), 256>>>(out);
}

// round 6
// speedup vs baseline: 2.8328x; 1.0407x over previous
#include <cuda_runtime.h>
#include <cuda_fp16.h>
#include <cstdint>

#define H_  32
#define N_  2048
#define T_  2048
#define D_  128
#define R_  64

// fp16 staging for keff only (q converted inline in the GEMM loader)
__device__ __align__(16) __half g_keffh[H_ * T_ * D_];   // 16.8 MB

// ---------------------------------------------------------------------------
// packed f32x2 helpers (Blackwell sm_100+ family, NOT 'a'-gated)
// ---------------------------------------------------------------------------
__device__ __forceinline__ uint64_t pack2(float lo, float hi) {
    uint64_t v; asm("mov.b64 %0, {%1, %2};" : "=l"(v) : "f"(lo), "f"(hi)); return v;
}
__device__ __forceinline__ void unpack2(uint64_t v, float& lo, float& hi) {
    asm("mov.b64 {%0, %1}, %2;" : "=f"(lo), "=f"(hi) : "l"(v));
}
__device__ __forceinline__ uint64_t ffma2(uint64_t a, uint64_t b, uint64_t c) {
    uint64_t d;
    asm("fma.rn.f32x2 %0, %1, %2, %3;" : "=l"(d) : "l"(a), "l"(b), "l"(c));
    return d;
}

// ---------------------------------------------------------------------------
// Prep kernel: per head, per 64-token chunk (exact fp32 math, f32x2 packed):
//   s[t,r]    = sign( sum_d (k_orig-k_quant)[t,d] * G[d,r] )
//   keff[t,d] = fp16( k_quant[t,d] + (1/64) * sum_r G[d,r] * s[t,r] )
// smem: sG [128][68] only (no transposed copy: stage-2's per-lane scalar
// G[d][r] read at stride 68 is 4-way conflicted = 4cyc, hidden under 32cyc
// of FFMA2 per r). 68.1 KB total -> 3 CTAs/SM.
// ---------------------------------------------------------------------------
#define SG_S  68
#define SE_S  65
#define SS_S  68

__global__ __launch_bounds__(256, 3) void qjl_prep_kernel(
    const float* __restrict__ k_orig,
    const float* __restrict__ k_quant,
    const float* __restrict__ G)
{
    extern __shared__ float sm[];
    float* sG = sm;                        // [128][SG_S]  (d, r)
    float* sE = sG + 128 * SG_S;           // [128][SE_S]  (d, t)
    float* sS = sE;                        // [64][SS_S]   (r, t)  aliases sE

    const int tid = threadIdx.x;
    const int h   = blockIdx.y;
    const int t0  = blockIdx.x * 64;

    for (int i = tid; i < D_ * R_; i += 256) {
        int d = i >> 6, r = i & 63;
        sG[d * SG_S + r] = G[i];
    }
    const float* ko = k_orig  + ((size_t)h * T_ + t0) * D_;
    const float* kq = k_quant + ((size_t)h * T_ + t0) * D_;
    for (int i = tid; i < 64 * D_; i += 256) {
        int t = i >> 7, d = i & 127;
        sE[d * SE_S + t] = ko[t * D_ + d] - kq[t * D_ + d];
    }
    __syncthreads();

    // ---- stage 1: s = sign(e @ G); thread = (tc, rg), 16 r's as 8 f32x2 pairs
    {
        const int tc = tid & 63;
        const int rg = tid >> 6;
        uint64_t acc[8];
        #pragma unroll
        for (int i = 0; i < 8; i++) acc[i] = pack2(0.f, 0.f);
        for (int d = 0; d < D_; d++) {
            float ev = sE[d * SE_S + tc];
            uint64_t ev2 = pack2(ev, ev);
            const ulonglong2* gp = (const ulonglong2*)(sG + d * SG_S + rg * 16);
            #pragma unroll
            for (int v = 0; v < 4; v++) {
                ulonglong2 g2 = gp[v];
                acc[v*2+0] = ffma2(ev2, g2.x, acc[v*2+0]);
                acc[v*2+1] = ffma2(ev2, g2.y, acc[v*2+1]);
            }
        }
        __syncthreads();   // all sE reads done before sS (alias) writes
        #pragma unroll
        for (int i = 0; i < 8; i++) {
            float a0, a1;
            unpack2(acc[i], a0, a1);
            float s0 = (a0 > 0.f) ? 1.f : ((a0 < 0.f) ? -1.f : 0.f);
            float s1 = (a1 > 0.f) ? 1.f : ((a1 < 0.f) ? -1.f : 0.f);
            sS[(rg * 16 + 2*i    ) * SS_S + tc] = s0;
            sS[(rg * 16 + 2*i + 1) * SS_S + tc] = s1;
        }
    }
    __syncthreads();

    // ---- stage 2: keff = fp16(kq + (G @ s^T)/64); thread = (d, tcg), 32 t's
    {
        const int d   = tid & 127;
        const int tcg = tid >> 7;
        uint64_t acc[16];
        #pragma unroll
        for (int j = 0; j < 16; j++) acc[j] = pack2(0.f, 0.f);
        for (int r = 0; r < R_; r++) {
            float gv = sG[d * SG_S + r];          // 4-way conflict, hidden
            uint64_t gv2 = pack2(gv, gv);
            const ulonglong2* sp = (const ulonglong2*)(sS + r * SS_S + tcg * 32);
            #pragma unroll
            for (int v = 0; v < 8; v++) {
                ulonglong2 s2 = sp[v];
                acc[v*2+0] = ffma2(gv2, s2.x, acc[v*2+0]);
                acc[v*2+1] = ffma2(gv2, s2.y, acc[v*2+1]);
            }
        }
        __half* ke = g_keffh + ((size_t)h * T_ + t0) * D_;
        const float scale = 1.f / 64.f;
        #pragma unroll
        for (int j = 0; j < 16; j++) {
            float a0, a1;
            unpack2(acc[j], a0, a1);
            int t0j = tcg * 32 + 2*j;
            ke[(t0j    ) * D_ + d] = __float2half_rn(kq[(t0j    ) * D_ + d] + a0 * scale);
            ke[(t0j + 1) * D_ + d] = __float2half_rn(kq[(t0j + 1) * D_ + d] + a1 * scale);
        }
    }
}

// ---------------------------------------------------------------------------
// Main GEMM: out[h,n,t] = sum_d q[h,n,d]*keff[h,t,d]  (fp16 mma, fp32 acc)
// Block 128x128, 256 threads, warp 64x32. K=128 fully resident in smem.
// A loaded as fp32 q and converted to fp16 inline (no separate qcvt kernel).
// Per-chunk swizzle: row stride 16 words, g' = g ^ ((row>>1)&3), 16B granules.
// Single __syncthreads; streaming (stcs) output stores.
// ---------------------------------------------------------------------------
#define NKT 4      // 128 / 32

__device__ __forceinline__ void mma_f16(float* c,
                                        uint32_t a0, uint32_t a1, uint32_t a2, uint32_t a3,
                                        uint32_t b0, uint32_t b1) {
    asm volatile(
        "mma.sync.aligned.m16n8k16.row.col.f32.f16.f16.f32 "
        "{%0,%1,%2,%3}, {%4,%5,%6,%7}, {%8,%9}, {%0,%1,%2,%3};\n"
        : "+f"(c[0]), "+f"(c[1]), "+f"(c[2]), "+f"(c[3])
        : "r"(a0), "r"(a1), "r"(a2), "r"(a3), "r"(b0), "r"(b1));
}

__device__ __forceinline__ uint32_t h2u(__half2 h) {
    union { __half2 h; uint32_t u; } c; c.h = h; return c.u;
}

__global__ __launch_bounds__(256, 2) void qjl_gemm_kernel(const float* __restrict__ q,
                                                          float* __restrict__ out)
{
    __shared__ __align__(16) uint32_t sA[NKT][128 * 16];
    __shared__ __align__(16) uint32_t sB[NKT][128 * 16];

    const int tid  = threadIdx.x;
    const int warp = tid >> 5;
    const int lane = tid & 31;
    const int h  = blockIdx.z;
    const int n0 = blockIdx.y * 128;
    const int t0 = blockIdx.x * 128;

    const float4* Af4 = (const float4*)(q       + ((size_t)h * N_ + n0) * D_);
    const uint4*  Bg4 = (const uint4*)(g_keffh + ((size_t)h * T_ + t0) * D_);

    const int lrow = tid >> 2;          // rows lrow, lrow+64
    const int q4   = tid & 3;           // 16B slot within a 32-half chunk
    const int rs0  = (lrow >> 1) & 3;   // same for lrow+64

#define STORE_CH(arr, row, rs, v)                                         \
    {                                                                     \
        uint32_t* p_ = &arr[(row) * 16 + q4];                             \
        p_[((0 ^ (rs)) << 2)] = (v).x;                                    \
        p_[((1 ^ (rs)) << 2)] = (v).y;                                    \
        p_[((2 ^ (rs)) << 2)] = (v).z;                                    \
        p_[((3 ^ (rs)) << 2)] = (v).w;                                    \
    }

    // load the entire K=128 tile (4 chunks), A converted fp32->fp16 inline
    #pragma unroll
    for (int kt = 0; kt < NKT; kt++) {
        float4 f0 = Af4[(size_t)lrow * 32 + kt * 8 + q4 * 2];
        float4 f1 = Af4[(size_t)lrow * 32 + kt * 8 + q4 * 2 + 1];
        float4 f2 = Af4[(size_t)(lrow + 64) * 32 + kt * 8 + q4 * 2];
        float4 f3 = Af4[(size_t)(lrow + 64) * 32 + kt * 8 + q4 * 2 + 1];
        uint4 b0 = Bg4[(size_t)lrow * 16 + kt * 4 + q4];
        uint4 b1 = Bg4[(size_t)(lrow + 64) * 16 + kt * 4 + q4];
        uint4 a0 = make_uint4(h2u(__floats2half2_rn(f0.x, f0.y)),
                              h2u(__floats2half2_rn(f0.z, f0.w)),
                              h2u(__floats2half2_rn(f1.x, f1.y)),
                              h2u(__floats2half2_rn(f1.z, f1.w)));
        uint4 a1 = make_uint4(h2u(__floats2half2_rn(f2.x, f2.y)),
                              h2u(__floats2half2_rn(f2.z, f2.w)),
                              h2u(__floats2half2_rn(f3.x, f3.y)),
                              h2u(__floats2half2_rn(f3.z, f3.w)));
        STORE_CH(sA[kt], lrow,      rs0, a0);
        STORE_CH(sA[kt], lrow + 64, rs0, a1);
        STORE_CH(sB[kt], lrow,      rs0, b0);
        STORE_CH(sB[kt], lrow + 64, rs0, b1);
    }
    __syncthreads();

    const int warp_m = (warp & 1) * 64;
    const int warp_n = (warp >> 1) * 32;
    const int lr = lane >> 2;
    const int lc = lane & 3;

    float acc[4][4][4];
    #pragma unroll
    for (int mi = 0; mi < 4; mi++)
        #pragma unroll
        for (int ni = 0; ni < 4; ni++)
            #pragma unroll
            for (int v = 0; v < 4; v++) acc[mi][ni][v] = 0.f;

    #pragma unroll
    for (int kt = 0; kt < NKT; kt++) {
        // B fragments: one LDS.128 per ni covers both k8-steps
        uint4 bf[4];
        #pragma unroll
        for (int ni = 0; ni < 4; ni++) {
            int row = warp_n + ni * 8 + lr;
            int g   = (lc ^ ((row >> 1) & 3)) << 2;
            bf[ni] = *(const uint4*)&sB[kt][row * 16 + g];
        }

        // A fragments half 0 (mi = 0,1)
        uint4 alo[2], ahi[2];
        #pragma unroll
        for (int mi = 0; mi < 2; mi++) {
            int row = warp_m + mi * 16 + lr;
            int g   = (lc ^ ((row >> 1) & 3)) << 2;
            alo[mi] = *(const uint4*)&sA[kt][row * 16 + g];
            ahi[mi] = *(const uint4*)&sA[kt][(row + 8) * 16 + g];
        }
        #pragma unroll
        for (int mi = 0; mi < 2; mi++)
            #pragma unroll
            for (int ni = 0; ni < 4; ni++) {
                mma_f16(acc[mi][ni], alo[mi].x, ahi[mi].x, alo[mi].y, ahi[mi].y,
                        bf[ni].x, bf[ni].y);
                mma_f16(acc[mi][ni], alo[mi].z, ahi[mi].z, alo[mi].w, ahi[mi].w,
                        bf[ni].z, bf[ni].w);
            }

        // A fragments half 1 (mi = 2,3)
        #pragma unroll
        for (int mi = 0; mi < 2; mi++) {
            int row = warp_m + (mi + 2) * 16 + lr;
            int g   = (lc ^ ((row >> 1) & 3)) << 2;
            alo[mi] = *(const uint4*)&sA[kt][row * 16 + g];
            ahi[mi] = *(const uint4*)&sA[kt][(row + 8) * 16 + g];
        }
        #pragma unroll
        for (int mi = 0; mi < 2; mi++)
            #pragma unroll
            for (int ni = 0; ni < 4; ni++) {
                mma_f16(acc[mi + 2][ni], alo[mi].x, ahi[mi].x, alo[mi].y, ahi[mi].y,
                        bf[ni].x, bf[ni].y);
                mma_f16(acc[mi + 2][ni], alo[mi].z, ahi[mi].z, alo[mi].w, ahi[mi].w,
                        bf[ni].z, bf[ni].w);
            }
    }

    // epilogue: streaming stores (no reuse of out; keep L2 for q/keff)
    float* Og = out + ((size_t)h * N_ + n0) * T_ + t0;
    #pragma unroll
    for (int mi = 0; mi < 4; mi++) {
        int row = warp_m + mi * 16 + lr;
        #pragma unroll
        for (int ni = 0; ni < 4; ni++) {
            int col = warp_n + ni * 8 + 2 * lc;
            __stcs((float2*)(Og + (size_t)row * T_ + col),
                   make_float2(acc[mi][ni][0], acc[mi][ni][1]));
            __stcs((float2*)(Og + (size_t)(row + 8) * T_ + col),
                   make_float2(acc[mi][ni][2], acc[mi][ni][3]));
        }
    }
#undef STORE_CH
}

// ---------------------------------------------------------------------------
extern "C" void kernel_launch(void* const* d_in, const int* in_sizes, int n_in,
                              void* d_out, int out_size)
{
    const float* q  = (const float*)d_in[0];
    const float* ko = (const float*)d_in[1];
    const float* kq = (const float*)d_in[2];
    const float* G  = (const float*)d_in[3];
    float* out = (float*)d_out;

    const size_t smem_prep = (128 * SG_S + 128 * SE_S) * sizeof(float);
    cudaFuncSetAttribute(qjl_prep_kernel, cudaFuncAttributeMaxDynamicSharedMemorySize,
                         (int)smem_prep);

    qjl_prep_kernel<<<dim3(T_ / 64, H_), 256, smem_prep>>>(ko, kq, G);
    qjl_gemm_kernel<<<dim3(T_ / 128, N_ / 128, H_), 256>>>(q, out);
}

// round 7
// speedup vs baseline: 2.8331x; 1.0001x over previous
#include <cuda_runtime.h>
#include <cuda_fp16.h>
#include <cstdint>

#define H_  32
#define N_  2048
#define T_  2048
#define D_  128
#define R_  64

// Fragment-permuted fp16 operand buffers (layout = exactly what the MMA
// threads load):  [h*16 + tile][kt(4)][row(128)][lc(4)] as uint4, where the
// uint4 for (row,kt,lc) = k-pair words {lc, lc+4, lc+8, lc+12} of that row's
// 32-half chunk kt.  (Same permutation as the proven R4/R5 smem layout.)
__device__ __align__(16) uint4 g_qA[H_ * 16 * 4 * 128 * 4];   // q, 16.8 MB
__device__ __align__(16) uint4 g_kB[H_ * 16 * 4 * 128 * 4];   // keff, 16.8 MB

// ---------------------------------------------------------------------------
// packed f32x2 helpers (Blackwell sm_100+ family, NOT 'a'-gated)
// ---------------------------------------------------------------------------
__device__ __forceinline__ uint64_t pack2(float lo, float hi) {
    uint64_t v; asm("mov.b64 %0, {%1, %2};" : "=l"(v) : "f"(lo), "f"(hi)); return v;
}
__device__ __forceinline__ void unpack2(uint64_t v, float& lo, float& hi) {
    asm("mov.b64 {%0, %1}, %2;" : "=f"(lo), "=f"(hi) : "l"(v));
}
__device__ __forceinline__ uint64_t ffma2(uint64_t a, uint64_t b, uint64_t c) {
    uint64_t d;
    asm("fma.rn.f32x2 %0, %1, %2, %3;" : "=l"(d) : "l"(a), "l"(b), "l"(c));
    return d;
}

__device__ __forceinline__ uint32_t h2u(__half2 h) {
    union { __half2 h; uint32_t u; } c; c.h = h; return c.u;
}

// ---------------------------------------------------------------------------
// q -> fp16, fragment-permuted. One thread per (row-chunk, kt): reads 32
// floats, writes 4 uint4 (64B contiguous).
// idx bits: [0:7) row, [7:9) kt, [9:..) hb = h*16 + nb
// ---------------------------------------------------------------------------
__global__ void qcvt_kernel(const float* __restrict__ q)
{
    int idx = blockIdx.x * blockDim.x + threadIdx.x;
    int row = idx & 127;
    int kt  = (idx >> 7) & 3;
    int hb  = idx >> 9;

    const float4* src = (const float4*)q + ((size_t)hb * 128 + row) * 32 + kt * 8;
    float4 r[8];
    #pragma unroll
    for (int j = 0; j < 8; j++) r[j] = src[j];

    const float* f = (const float*)r;
    uint4* dst = g_qA + ((size_t)hb * 4 + kt) * 512 + row * 4;
    #pragma unroll
    for (int lc = 0; lc < 4; lc++) {
        uint4 o;
        // words lc, lc+4, lc+8, lc+12 ; word w = halves (2w, 2w+1)
        o.x = h2u(__floats2half2_rn(f[2*(lc     )], f[2*(lc     ) + 1]));
        o.y = h2u(__floats2half2_rn(f[2*(lc + 4 )], f[2*(lc + 4 ) + 1]));
        o.z = h2u(__floats2half2_rn(f[2*(lc + 8 )], f[2*(lc + 8 ) + 1]));
        o.w = h2u(__floats2half2_rn(f[2*(lc + 12)], f[2*(lc + 12) + 1]));
        dst[lc] = o;
    }
}

// ---------------------------------------------------------------------------
// Prep kernel: per head, per 64-token chunk (exact fp32 math, f32x2 packed):
//   s[t,r]    = sign( sum_d (k_orig-k_quant)[t,d] * G[d,r] )
//   keff[t,d] = fp16( k_quant[t,d] + (1/64) * sum_r G[d,r] * s[t,r] )
// keff written directly into the fragment-permuted g_kB layout.
// ---------------------------------------------------------------------------
#define SG_S  68
#define SE_S  65
#define SS_S  68

__global__ __launch_bounds__(256, 3) void qjl_prep_kernel(
    const float* __restrict__ k_orig,
    const float* __restrict__ k_quant,
    const float* __restrict__ G)
{
    extern __shared__ float sm[];
    float* sG = sm;                        // [128][SG_S]  (d, r)
    float* sE = sG + 128 * SG_S;           // [128][SE_S]  (d, t)
    float* sS = sE;                        // [64][SS_S]   (r, t)  aliases sE

    const int tid = threadIdx.x;
    const int h   = blockIdx.y;
    const int t0  = blockIdx.x * 64;

    for (int i = tid; i < D_ * R_; i += 256) {
        int d = i >> 6, r = i & 63;
        sG[d * SG_S + r] = G[i];
    }
    const float* ko = k_orig  + ((size_t)h * T_ + t0) * D_;
    const float* kq = k_quant + ((size_t)h * T_ + t0) * D_;
    for (int i = tid; i < 64 * D_; i += 256) {
        int t = i >> 7, d = i & 127;
        sE[d * SE_S + t] = ko[t * D_ + d] - kq[t * D_ + d];
    }
    __syncthreads();

    // ---- stage 1: s = sign(e @ G); thread = (tc, rg), 16 r's as 8 f32x2 pairs
    {
        const int tc = tid & 63;
        const int rg = tid >> 6;
        uint64_t acc[8];
        #pragma unroll
        for (int i = 0; i < 8; i++) acc[i] = pack2(0.f, 0.f);
        for (int d = 0; d < D_; d++) {
            float ev = sE[d * SE_S + tc];
            uint64_t ev2 = pack2(ev, ev);
            const ulonglong2* gp = (const ulonglong2*)(sG + d * SG_S + rg * 16);
            #pragma unroll
            for (int v = 0; v < 4; v++) {
                ulonglong2 g2 = gp[v];
                acc[v*2+0] = ffma2(ev2, g2.x, acc[v*2+0]);
                acc[v*2+1] = ffma2(ev2, g2.y, acc[v*2+1]);
            }
        }
        __syncthreads();   // all sE reads done before sS (alias) writes
        #pragma unroll
        for (int i = 0; i < 8; i++) {
            float a0, a1;
            unpack2(acc[i], a0, a1);
            float s0 = (a0 > 0.f) ? 1.f : ((a0 < 0.f) ? -1.f : 0.f);
            float s1 = (a1 > 0.f) ? 1.f : ((a1 < 0.f) ? -1.f : 0.f);
            sS[(rg * 16 + 2*i    ) * SS_S + tc] = s0;
            sS[(rg * 16 + 2*i + 1) * SS_S + tc] = s1;
        }
    }
    __syncthreads();

    // ---- stage 2: keff = fp16(kq + (G @ s^T)/64); thread = (d, tcg), 32 t's
    {
        const int d   = tid & 127;
        const int tcg = tid >> 7;
        uint64_t acc[16];
        #pragma unroll
        for (int j = 0; j < 16; j++) acc[j] = pack2(0.f, 0.f);
        for (int r = 0; r < R_; r++) {
            float gv = sG[d * SG_S + r];          // 4-way conflict, hidden
            uint64_t gv2 = pack2(gv, gv);
            const ulonglong2* sp = (const ulonglong2*)(sS + r * SS_S + tcg * 32);
            #pragma unroll
            for (int v = 0; v < 8; v++) {
                ulonglong2 s2 = sp[v];
                acc[v*2+0] = ffma2(gv2, s2.x, acc[v*2+0]);
                acc[v*2+1] = ffma2(gv2, s2.y, acc[v*2+1]);
            }
        }
        // permuted-store coordinates for this d
        const int kt   = d >> 5;
        const int w    = (d >> 1) & 15;
        const int lcq  = w & 3;
        const int p    = w >> 2;
        const int hoff = d & 1;
        const int tb      = (h << 4) + (t0 >> 7);
        const int rowbase = (t0 & 127) + tcg * 32;
        __half* base = (__half*)g_kB
                     + ((size_t)(tb * 4 + kt) * 128) * 32 + lcq * 8 + p * 2 + hoff;
        const float scale = 1.f / 64.f;
        #pragma unroll
        for (int j = 0; j < 16; j++) {
            float a0, a1;
            unpack2(acc[j], a0, a1);
            int trel = tcg * 32 + 2*j;
            base[(size_t)(rowbase + 2*j    ) * 32] =
                __float2half_rn(kq[(trel    ) * D_ + d] + a0 * scale);
            base[(size_t)(rowbase + 2*j + 1) * 32] =
                __float2half_rn(kq[(trel + 1) * D_ + d] + a1 * scale);
        }
    }
}

// ---------------------------------------------------------------------------
// Main GEMM, smem-free: fragments loaded straight from the pre-permuted
// gmem buffers (L1/L2 absorb the 4x/2x cross-warp redundancy).
// Block tile 128x128, 256 threads, warp tile 64x32. No barriers at all.
// ---------------------------------------------------------------------------
__device__ __forceinline__ void mma_f16(float* c,
                                        uint32_t a0, uint32_t a1, uint32_t a2, uint32_t a3,
                                        uint32_t b0, uint32_t b1) {
    asm volatile(
        "mma.sync.aligned.m16n8k16.row.col.f32.f16.f16.f32 "
        "{%0,%1,%2,%3}, {%4,%5,%6,%7}, {%8,%9}, {%0,%1,%2,%3};\n"
        : "+f"(c[0]), "+f"(c[1]), "+f"(c[2]), "+f"(c[3])
        : "r"(a0), "r"(a1), "r"(a2), "r"(a3), "r"(b0), "r"(b1));
}

__global__ __launch_bounds__(256, 2) void qjl_gemm_kernel(float* __restrict__ out)
{
    const int tid  = threadIdx.x;
    const int warp = tid >> 5;
    const int lane = tid & 31;
    const int h  = blockIdx.z;
    const int nb = blockIdx.y;
    const int tb = blockIdx.x;

    const uint4* __restrict__ Ab = g_qA + (size_t)((h << 4) + nb) * 2048;
    const uint4* __restrict__ Bb = g_kB + (size_t)((h << 4) + tb) * 2048;

    const int warp_m = (warp & 1) * 64;
    const int warp_n = (warp >> 1) * 32;
    const int lr = lane >> 2;
    const int lc = lane & 3;

    float acc[4][4][4];
    #pragma unroll
    for (int mi = 0; mi < 4; mi++)
        #pragma unroll
        for (int ni = 0; ni < 4; ni++)
            #pragma unroll
            for (int v = 0; v < 4; v++) acc[mi][ni][v] = 0.f;

    #pragma unroll
    for (int kt = 0; kt < 4; kt++) {
        const uint4* Akt = Ab + kt * 512;
        const uint4* Bkt = Bb + kt * 512;

        // B fragments: one LDG.128 per ni covers both k8-steps
        uint4 bf[4];
        #pragma unroll
        for (int ni = 0; ni < 4; ni++)
            bf[ni] = Bkt[(warp_n + ni * 8 + lr) * 4 + lc];

        // A fragments half 0 (mi = 0,1)
        uint4 alo[2], ahi[2];
        #pragma unroll
        for (int mi = 0; mi < 2; mi++) {
            int row = warp_m + mi * 16 + lr;
            alo[mi] = Akt[row * 4 + lc];
            ahi[mi] = Akt[(row + 8) * 4 + lc];
        }
        #pragma unroll
        for (int mi = 0; mi < 2; mi++)
            #pragma unroll
            for (int ni = 0; ni < 4; ni++) {
                mma_f16(acc[mi][ni], alo[mi].x, ahi[mi].x, alo[mi].y, ahi[mi].y,
                        bf[ni].x, bf[ni].y);
                mma_f16(acc[mi][ni], alo[mi].z, ahi[mi].z, alo[mi].w, ahi[mi].w,
                        bf[ni].z, bf[ni].w);
            }

        // A fragments half 1 (mi = 2,3)
        #pragma unroll
        for (int mi = 0; mi < 2; mi++) {
            int row = warp_m + (mi + 2) * 16 + lr;
            alo[mi] = Akt[row * 4 + lc];
            ahi[mi] = Akt[(row + 8) * 4 + lc];
        }
        #pragma unroll
        for (int mi = 0; mi < 2; mi++)
            #pragma unroll
            for (int ni = 0; ni < 4; ni++) {
                mma_f16(acc[mi + 2][ni], alo[mi].x, ahi[mi].x, alo[mi].y, ahi[mi].y,
                        bf[ni].x, bf[ni].y);
                mma_f16(acc[mi + 2][ni], alo[mi].z, ahi[mi].z, alo[mi].w, ahi[mi].w,
                        bf[ni].z, bf[ni].w);
            }
    }

    // epilogue: streaming stores
    float* Og = out + ((size_t)h * N_ + nb * 128) * T_ + tb * 128;
    #pragma unroll
    for (int mi = 0; mi < 4; mi++) {
        int row = warp_m + mi * 16 + lr;
        #pragma unroll
        for (int ni = 0; ni < 4; ni++) {
            int col = warp_n + ni * 8 + 2 * lc;
            __stcs((float2*)(Og + (size_t)row * T_ + col),
                   make_float2(acc[mi][ni][0], acc[mi][ni][1]));
            __stcs((float2*)(Og + (size_t)(row + 8) * T_ + col),
                   make_float2(acc[mi][ni][2], acc[mi][ni][3]));
        }
    }
}

// ---------------------------------------------------------------------------
extern "C" void kernel_launch(void* const* d_in, const int* in_sizes, int n_in,
                              void* d_out, int out_size)
{
    const float* q  = (const float*)d_in[0];
    const float* ko = (const float*)d_in[1];
    const float* kq = (const float*)d_in[2];
    const float* G  = (const float*)d_in[3];
    float* out = (float*)d_out;

    const size_t smem_prep = (128 * SG_S + 128 * SE_S) * sizeof(float);
    cudaFuncSetAttribute(qjl_prep_kernel, cudaFuncAttributeMaxDynamicSharedMemorySize,
                         (int)smem_prep);

    qcvt_kernel<<<(H_ * N_ * 4) / 256, 256>>>(q);
    qjl_prep_kernel<<<dim3(T_ / 64, H_), 256, smem_prep>>>(ko, kq, G);
    qjl_gemm_kernel<<<dim3(T_ / 128, N_ / 128, H_), 256>>>(out);
}

// round 8
// speedup vs baseline: 2.8996x; 1.0235x over previous
#include <cuda_runtime.h>
#include <cuda_fp16.h>
#include <cstdint>

#define H_  32
#define N_  2048
#define T_  2048
#define D_  128
#define R_  64

// Fragment-permuted fp16 operand buffers:
//   g_qA: [h*16 + nb][kt(4)][row(128)][lc(4)] uint4 — row = output n (identity)
//   g_kB: same shape, but token t stored at fragment row rho(t) so that the
//         MMA output fragment becomes 16B-contiguous in the output:
//         rho(t) = (2*(t>>4) + ((t>>1)&1))*8 + ((t>>2)&3)*2 + (t&1)
__device__ __align__(16) uint4 g_qA[H_ * 16 * 4 * 128 * 4];   // 16.8 MB
__device__ __align__(16) uint4 g_kB[H_ * 16 * 4 * 128 * 4];   // 16.8 MB

// ---------------------------------------------------------------------------
// packed f32x2 helpers (Blackwell sm_100+ family, NOT 'a'-gated)
// ---------------------------------------------------------------------------
__device__ __forceinline__ uint64_t pack2(float lo, float hi) {
    uint64_t v; asm("mov.b64 %0, {%1, %2};" : "=l"(v) : "f"(lo), "f"(hi)); return v;
}
__device__ __forceinline__ void unpack2(uint64_t v, float& lo, float& hi) {
    asm("mov.b64 {%0, %1}, %2;" : "=f"(lo), "=f"(hi) : "l"(v));
}
__device__ __forceinline__ uint64_t ffma2(uint64_t a, uint64_t b, uint64_t c) {
    uint64_t d;
    asm("fma.rn.f32x2 %0, %1, %2, %3;" : "=l"(d) : "l"(a), "l"(b), "l"(c));
    return d;
}

__device__ __forceinline__ uint32_t h2u(__half2 h) {
    union { __half2 h; uint32_t u; } c; c.h = h; return c.u;
}

// ---------------------------------------------------------------------------
// q -> fp16, fragment-permuted (identity row mapping).
// ---------------------------------------------------------------------------
__global__ void qcvt_kernel(const float* __restrict__ q)
{
    int idx = blockIdx.x * blockDim.x + threadIdx.x;
    int row = idx & 127;
    int kt  = (idx >> 7) & 3;
    int hb  = idx >> 9;

    const float4* src = (const float4*)q + ((size_t)hb * 128 + row) * 32 + kt * 8;
    float4 r[8];
    #pragma unroll
    for (int j = 0; j < 8; j++) r[j] = src[j];

    const float* f = (const float*)r;
    uint4* dst = g_qA + ((size_t)hb * 4 + kt) * 512 + row * 4;
    #pragma unroll
    for (int lc = 0; lc < 4; lc++) {
        uint4 o;
        o.x = h2u(__floats2half2_rn(f[2*(lc     )], f[2*(lc     ) + 1]));
        o.y = h2u(__floats2half2_rn(f[2*(lc + 4 )], f[2*(lc + 4 ) + 1]));
        o.z = h2u(__floats2half2_rn(f[2*(lc + 8 )], f[2*(lc + 8 ) + 1]));
        o.w = h2u(__floats2half2_rn(f[2*(lc + 12)], f[2*(lc + 12) + 1]));
        dst[lc] = o;
    }
}

// ---------------------------------------------------------------------------
// Prep kernel: per head, per 64-token chunk (exact fp32 math, f32x2 packed):
//   s[t,r]    = sign( sum_d (k_orig-k_quant)[t,d] * G[d,r] )
//   keff[t,d] = fp16( k_quant[t,d] + (1/64) * sum_r G[d,r] * s[t,r] )
// keff written into g_kB at fragment row rho(t) (output-contiguity permutation).
// ---------------------------------------------------------------------------
#define SG_S  68
#define SE_S  65
#define SS_S  68

__global__ __launch_bounds__(256, 3) void qjl_prep_kernel(
    const float* __restrict__ k_orig,
    const float* __restrict__ k_quant,
    const float* __restrict__ G)
{
    extern __shared__ float sm[];
    float* sG = sm;                        // [128][SG_S]  (d, r)
    float* sE = sG + 128 * SG_S;           // [128][SE_S]  (d, t)
    float* sS = sE;                        // [64][SS_S]   (r, t)  aliases sE

    const int tid = threadIdx.x;
    const int h   = blockIdx.y;
    const int t0  = blockIdx.x * 64;

    for (int i = tid; i < D_ * R_; i += 256) {
        int d = i >> 6, r = i & 63;
        sG[d * SG_S + r] = G[i];
    }
    const float* ko = k_orig  + ((size_t)h * T_ + t0) * D_;
    const float* kq = k_quant + ((size_t)h * T_ + t0) * D_;
    for (int i = tid; i < 64 * D_; i += 256) {
        int t = i >> 7, d = i & 127;
        sE[d * SE_S + t] = ko[t * D_ + d] - kq[t * D_ + d];
    }
    __syncthreads();

    // ---- stage 1: s = sign(e @ G); thread = (tc, rg), 16 r's as 8 f32x2 pairs
    {
        const int tc = tid & 63;
        const int rg = tid >> 6;
        uint64_t acc[8];
        #pragma unroll
        for (int i = 0; i < 8; i++) acc[i] = pack2(0.f, 0.f);
        for (int d = 0; d < D_; d++) {
            float ev = sE[d * SE_S + tc];
            uint64_t ev2 = pack2(ev, ev);
            const ulonglong2* gp = (const ulonglong2*)(sG + d * SG_S + rg * 16);
            #pragma unroll
            for (int v = 0; v < 4; v++) {
                ulonglong2 g2 = gp[v];
                acc[v*2+0] = ffma2(ev2, g2.x, acc[v*2+0]);
                acc[v*2+1] = ffma2(ev2, g2.y, acc[v*2+1]);
            }
        }
        __syncthreads();   // all sE reads done before sS (alias) writes
        #pragma unroll
        for (int i = 0; i < 8; i++) {
            float a0, a1;
            unpack2(acc[i], a0, a1);
            float s0 = (a0 > 0.f) ? 1.f : ((a0 < 0.f) ? -1.f : 0.f);
            float s1 = (a1 > 0.f) ? 1.f : ((a1 < 0.f) ? -1.f : 0.f);
            sS[(rg * 16 + 2*i    ) * SS_S + tc] = s0;
            sS[(rg * 16 + 2*i + 1) * SS_S + tc] = s1;
        }
    }
    __syncthreads();

    // ---- stage 2: keff = fp16(kq + (G @ s^T)/64); thread = (d, tcg), 32 t's
    {
        const int d   = tid & 127;
        const int tcg = tid >> 7;
        uint64_t acc[16];
        #pragma unroll
        for (int j = 0; j < 16; j++) acc[j] = pack2(0.f, 0.f);
        for (int r = 0; r < R_; r++) {
            float gv = sG[d * SG_S + r];          // 4-way conflict, hidden
            uint64_t gv2 = pack2(gv, gv);
            const ulonglong2* sp = (const ulonglong2*)(sS + r * SS_S + tcg * 32);
            #pragma unroll
            for (int v = 0; v < 8; v++) {
                ulonglong2 s2 = sp[v];
                acc[v*2+0] = ffma2(gv2, s2.x, acc[v*2+0]);
                acc[v*2+1] = ffma2(gv2, s2.y, acc[v*2+1]);
            }
        }
        // permuted-store coordinates for this d (within the 32-half chunk kt)
        const int kt   = d >> 5;
        const int w    = (d >> 1) & 15;
        const int lcq  = w & 3;
        const int p    = w >> 2;
        const int hoff = d & 1;
        const int tb   = (h << 4) + (t0 >> 7);
        __half* basep = (__half*)g_kB
                      + ((size_t)(tb * 4 + kt) * 128) * 32 + lcq * 8 + p * 2 + hoff;
        const float scale = 1.f / 64.f;
        #pragma unroll
        for (int j = 0; j < 16; j++) {
            float a0, a1;
            unpack2(acc[j], a0, a1);
            int trel = tcg * 32 + 2*j;
            #pragma unroll
            for (int b = 0; b < 2; b++) {
                int tl  = (t0 & 127) + trel + b;    // token within 128-tile
                int row = (2 * (tl >> 4) + ((tl >> 1) & 1)) * 8
                        + ((tl >> 2) & 3) * 2 + (tl & 1);      // rho(tl)
                float av = b ? a1 : a0;
                basep[(size_t)row * 32] =
                    __float2half_rn(kq[(trel + b) * D_ + d] + av * scale);
            }
        }
    }
}

// ---------------------------------------------------------------------------
// Main GEMM, smem-free, barrier-free. Block 128x128, warp 64x32.
// B rows carry the rho() permutation -> epilogue is STG.128 (16B/lane/row),
// halving store wavefronts vs scattered STG.64.
// ---------------------------------------------------------------------------
__device__ __forceinline__ void mma_f16(float* c,
                                        uint32_t a0, uint32_t a1, uint32_t a2, uint32_t a3,
                                        uint32_t b0, uint32_t b1) {
    asm volatile(
        "mma.sync.aligned.m16n8k16.row.col.f32.f16.f16.f32 "
        "{%0,%1,%2,%3}, {%4,%5,%6,%7}, {%8,%9}, {%0,%1,%2,%3};\n"
        : "+f"(c[0]), "+f"(c[1]), "+f"(c[2]), "+f"(c[3])
        : "r"(a0), "r"(a1), "r"(a2), "r"(a3), "r"(b0), "r"(b1));
}

__global__ __launch_bounds__(256, 2) void qjl_gemm_kernel(float* __restrict__ out)
{
    const int tid  = threadIdx.x;
    const int warp = tid >> 5;
    const int lane = tid & 31;
    const int h  = blockIdx.z;
    const int nb = blockIdx.y;
    const int tb = blockIdx.x;

    const uint4* __restrict__ Ab = g_qA + (size_t)((h << 4) + nb) * 2048;
    const uint4* __restrict__ Bb = g_kB + (size_t)((h << 4) + tb) * 2048;

    const int warp_m = (warp & 1) * 64;
    const int warp_n = (warp >> 1) * 32;
    const int lr = lane >> 2;
    const int lc = lane & 3;

    float acc[4][4][4];
    #pragma unroll
    for (int mi = 0; mi < 4; mi++)
        #pragma unroll
        for (int ni = 0; ni < 4; ni++)
            #pragma unroll
            for (int v = 0; v < 4; v++) acc[mi][ni][v] = 0.f;

    #pragma unroll
    for (int kt = 0; kt < 4; kt++) {
        const uint4* Akt = Ab + kt * 512;
        const uint4* Bkt = Bb + kt * 512;

        // B fragments: one LDG.128 per ni covers both k8-steps
        uint4 bf[4];
        #pragma unroll
        for (int ni = 0; ni < 4; ni++)
            bf[ni] = Bkt[(warp_n + ni * 8 + lr) * 4 + lc];

        // A fragments half 0 (mi = 0,1)
        uint4 alo[2], ahi[2];
        #pragma unroll
        for (int mi = 0; mi < 2; mi++) {
            int row = warp_m + mi * 16 + lr;
            alo[mi] = Akt[row * 4 + lc];
            ahi[mi] = Akt[(row + 8) * 4 + lc];
        }
        #pragma unroll
        for (int mi = 0; mi < 2; mi++)
            #pragma unroll
            for (int ni = 0; ni < 4; ni++) {
                mma_f16(acc[mi][ni], alo[mi].x, ahi[mi].x, alo[mi].y, ahi[mi].y,
                        bf[ni].x, bf[ni].y);
                mma_f16(acc[mi][ni], alo[mi].z, ahi[mi].z, alo[mi].w, ahi[mi].w,
                        bf[ni].z, bf[ni].w);
            }

        // A fragments half 1 (mi = 2,3)
        #pragma unroll
        for (int mi = 0; mi < 2; mi++) {
            int row = warp_m + (mi + 2) * 16 + lr;
            alo[mi] = Akt[row * 4 + lc];
            ahi[mi] = Akt[(row + 8) * 4 + lc];
        }
        #pragma unroll
        for (int mi = 0; mi < 2; mi++)
            #pragma unroll
            for (int ni = 0; ni < 4; ni++) {
                mma_f16(acc[mi + 2][ni], alo[mi].x, ahi[mi].x, alo[mi].y, ahi[mi].y,
                        bf[ni].x, bf[ni].y);
                mma_f16(acc[mi + 2][ni], alo[mi].z, ahi[mi].z, alo[mi].w, ahi[mi].w,
                        bf[ni].z, bf[ni].w);
            }
    }

    // epilogue: token-permuted fragments -> 16B-contiguous STG.128 per lane.
    // Pair (ni=2j, 2j+1) holds tokens {warp_n+16j+4lc .. +3} in order
    // (acc[2j][0], acc[2j][1], acc[2j+1][0], acc[2j+1][1]) (rows lr),
    // and ([2],[3]) for rows lr+8.
    float* Og = out + ((size_t)h * N_ + nb * 128) * T_ + tb * 128;
    #pragma unroll
    for (int mi = 0; mi < 4; mi++) {
        int row = warp_m + mi * 16 + lr;
        #pragma unroll
        for (int j = 0; j < 2; j++) {
            int col = warp_n + 16 * j + 4 * lc;
            float4 v0 = make_float4(acc[mi][2*j][0], acc[mi][2*j][1],
                                    acc[mi][2*j+1][0], acc[mi][2*j+1][1]);
            float4 v1 = make_float4(acc[mi][2*j][2], acc[mi][2*j][3],
                                    acc[mi][2*j+1][2], acc[mi][2*j+1][3]);
            __stcs((float4*)(Og + (size_t)row * T_ + col), v0);
            __stcs((float4*)(Og + (size_t)(row + 8) * T_ + col), v1);
        }
    }
}

// ---------------------------------------------------------------------------
extern "C" void kernel_launch(void* const* d_in, const int* in_sizes, int n_in,
                              void* d_out, int out_size)
{
    const float* q  = (const float*)d_in[0];
    const float* ko = (const float*)d_in[1];
    const float* kq = (const float*)d_in[2];
    const float* G  = (const float*)d_in[3];
    float* out = (float*)d_out;

    const size_t smem_prep = (128 * SG_S + 128 * SE_S) * sizeof(float);
    cudaFuncSetAttribute(qjl_prep_kernel, cudaFuncAttributeMaxDynamicSharedMemorySize,
                         (int)smem_prep);

    qcvt_kernel<<<(H_ * N_ * 4) / 256, 256>>>(q);
    qjl_prep_kernel<<<dim3(T_ / 64, H_), 256, smem_prep>>>(ko, kq, G);
    qjl_gemm_kernel<<<dim3(T_ / 128, N_ / 128, H_), 256>>>(out);
}

// round 10
// speedup vs baseline: 3.0032x; 1.0357x over previous
#include <cuda_runtime.h>
#include <cuda_fp16.h>
#include <cstdint>

#define H_  32
#define N_  2048
#define T_  2048
#define D_  128
#define R_  64

// Fragment-permuted fp16 operand buffers:
//   g_qA: [h*16 + nb][kt(4)][row(128)][lc(4)] uint4 — row = output n (identity)
//   g_kB: same shape, but token t stored at fragment row rho(t) so that the
//         MMA output fragment becomes 16B-contiguous in the output:
//         rho(t) = (2*(t>>4) + ((t>>1)&1))*8 + ((t>>2)&3)*2 + (t&1)
__device__ __align__(16) uint4 g_qA[H_ * 16 * 4 * 128 * 4];   // 16.8 MB
__device__ __align__(16) uint4 g_kB[H_ * 16 * 4 * 128 * 4];   // 16.8 MB

// ---------------------------------------------------------------------------
// packed f32x2 helpers (Blackwell sm_100+ family, NOT 'a'-gated)
// ---------------------------------------------------------------------------
__device__ __forceinline__ uint64_t pack2(float lo, float hi) {
    uint64_t v; asm("mov.b64 %0, {%1, %2};" : "=l"(v) : "f"(lo), "f"(hi)); return v;
}
__device__ __forceinline__ void unpack2(uint64_t v, float& lo, float& hi) {
    asm("mov.b64 {%0, %1}, %2;" : "=f"(lo), "=f"(hi) : "l"(v));
}
__device__ __forceinline__ uint64_t ffma2(uint64_t a, uint64_t b, uint64_t c) {
    uint64_t d;
    asm("fma.rn.f32x2 %0, %1, %2, %3;" : "=l"(d) : "l"(a), "l"(b), "l"(c));
    return d;
}

__device__ __forceinline__ uint32_t h2u(__half2 h) {
    union { __half2 h; uint32_t u; } c; c.h = h; return c.u;
}

// ---------------------------------------------------------------------------
// q -> fp16, fragment-permuted (identity row mapping).
// ---------------------------------------------------------------------------
__global__ void qcvt_kernel(const float* __restrict__ q)
{
    int idx = blockIdx.x * blockDim.x + threadIdx.x;
    int row = idx & 127;
    int kt  = (idx >> 7) & 3;
    int hb  = idx >> 9;

    const float4* src = (const float4*)q + ((size_t)hb * 128 + row) * 32 + kt * 8;
    float4 r[8];
    #pragma unroll
    for (int j = 0; j < 8; j++) r[j] = src[j];

    const float* f = (const float*)r;
    uint4* dst = g_qA + ((size_t)hb * 4 + kt) * 512 + row * 4;
    #pragma unroll
    for (int lc = 0; lc < 4; lc++) {
        uint4 o;
        o.x = h2u(__floats2half2_rn(f[2*(lc     )], f[2*(lc     ) + 1]));
        o.y = h2u(__floats2half2_rn(f[2*(lc + 4 )], f[2*(lc + 4 ) + 1]));
        o.z = h2u(__floats2half2_rn(f[2*(lc + 8 )], f[2*(lc + 8 ) + 1]));
        o.w = h2u(__floats2half2_rn(f[2*(lc + 12)], f[2*(lc + 12) + 1]));
        dst[lc] = o;
    }
}

// ---------------------------------------------------------------------------
// Prep kernel: per head, per 64-token chunk (exact fp32 math, f32x2 packed):
//   s[t,r]    = sign( sum_d (k_orig-k_quant)[t,d] * G[d,r] )
//   keff[t,d] = fp16( k_quant[t,d] + (1/64) * sum_r G[d,r] * s[t,r] )
// keff written into g_kB at fragment row rho(t) (output-contiguity permutation).
// ---------------------------------------------------------------------------
#define SG_S  68
#define SE_S  65
#define SS_S  68

__global__ __launch_bounds__(256, 3) void qjl_prep_kernel(
    const float* __restrict__ k_orig,
    const float* __restrict__ k_quant,
    const float* __restrict__ G)
{
    extern __shared__ float sm[];
    float* sG = sm;                        // [128][SG_S]  (d, r)
    float* sE = sG + 128 * SG_S;           // [128][SE_S]  (d, t)
    float* sS = sE;                        // [64][SS_S]   (r, t)  aliases sE

    const int tid = threadIdx.x;
    const int h   = blockIdx.y;
    const int t0  = blockIdx.x * 64;

    for (int i = tid; i < D_ * R_; i += 256) {
        int d = i >> 6, r = i & 63;
        sG[d * SG_S + r] = G[i];
    }
    const float* ko = k_orig  + ((size_t)h * T_ + t0) * D_;
    const float* kq = k_quant + ((size_t)h * T_ + t0) * D_;
    for (int i = tid; i < 64 * D_; i += 256) {
        int t = i >> 7, d = i & 127;
        sE[d * SE_S + t] = ko[t * D_ + d] - kq[t * D_ + d];
    }
    __syncthreads();

    // ---- stage 1: s = sign(e @ G); thread = (tc, rg), 16 r's as 8 f32x2 pairs
    {
        const int tc = tid & 63;
        const int rg = tid >> 6;
        uint64_t acc[8];
        #pragma unroll
        for (int i = 0; i < 8; i++) acc[i] = pack2(0.f, 0.f);
        for (int d = 0; d < D_; d++) {
            float ev = sE[d * SE_S + tc];
            uint64_t ev2 = pack2(ev, ev);
            const ulonglong2* gp = (const ulonglong2*)(sG + d * SG_S + rg * 16);
            #pragma unroll
            for (int v = 0; v < 4; v++) {
                ulonglong2 g2 = gp[v];
                acc[v*2+0] = ffma2(ev2, g2.x, acc[v*2+0]);
                acc[v*2+1] = ffma2(ev2, g2.y, acc[v*2+1]);
            }
        }
        __syncthreads();   // all sE reads done before sS (alias) writes
        #pragma unroll
        for (int i = 0; i < 8; i++) {
            float a0, a1;
            unpack2(acc[i], a0, a1);
            float s0 = (a0 > 0.f) ? 1.f : ((a0 < 0.f) ? -1.f : 0.f);
            float s1 = (a1 > 0.f) ? 1.f : ((a1 < 0.f) ? -1.f : 0.f);
            sS[(rg * 16 + 2*i    ) * SS_S + tc] = s0;
            sS[(rg * 16 + 2*i + 1) * SS_S + tc] = s1;
        }
    }
    __syncthreads();

    // ---- stage 2: keff = fp16(kq + (G @ s^T)/64); thread = (d, tcg), 32 t's
    {
        const int d   = tid & 127;
        const int tcg = tid >> 7;
        uint64_t acc[16];
        #pragma unroll
        for (int j = 0; j < 16; j++) acc[j] = pack2(0.f, 0.f);
        for (int r = 0; r < R_; r++) {
            float gv = sG[d * SG_S + r];          // 4-way conflict, hidden
            uint64_t gv2 = pack2(gv, gv);
            const ulonglong2* sp = (const ulonglong2*)(sS + r * SS_S + tcg * 32);
            #pragma unroll
            for (int v = 0; v < 8; v++) {
                ulonglong2 s2 = sp[v];
                acc[v*2+0] = ffma2(gv2, s2.x, acc[v*2+0]);
                acc[v*2+1] = ffma2(gv2, s2.y, acc[v*2+1]);
            }
        }
        // permuted-store coordinates for this d (within the 32-half chunk kt)
        const int kt   = d >> 5;
        const int w    = (d >> 1) & 15;
        const int lcq  = w & 3;
        const int p    = w >> 2;
        const int hoff = d & 1;
        const int tb   = (h << 4) + (t0 >> 7);
        __half* basep = (__half*)g_kB
                      + ((size_t)(tb * 4 + kt) * 128) * 32 + lcq * 8 + p * 2 + hoff;
        const float scale = 1.f / 64.f;
        #pragma unroll
        for (int j = 0; j < 16; j++) {
            float a0, a1;
            unpack2(acc[j], a0, a1);
            int trel = tcg * 32 + 2*j;
            #pragma unroll
            for (int b = 0; b < 2; b++) {
                int tl  = (t0 & 127) + trel + b;    // token within 128-tile
                int row = (2 * (tl >> 4) + ((tl >> 1) & 1)) * 8
                        + ((tl >> 2) & 3) * 2 + (tl & 1);      // rho(tl)
                float av = b ? a1 : a0;
                basep[(size_t)row * 32] =
                    __float2half_rn(kq[(trel + b) * D_ + d] + av * scale);
            }
        }
    }
}

// ---------------------------------------------------------------------------
// Main GEMM, smem-free, barrier-free. Block tile 64x128, 8 warps (2x4),
// warp tile 32x32 -> acc 32 regs, ~84 live regs, 3 CTAs/SM (24 warps).
// B rows carry the rho() permutation -> STG.128 epilogue.
// ---------------------------------------------------------------------------
__device__ __forceinline__ void mma_f16(float* c,
                                        uint32_t a0, uint32_t a1, uint32_t a2, uint32_t a3,
                                        uint32_t b0, uint32_t b1) {
    asm volatile(
        "mma.sync.aligned.m16n8k16.row.col.f32.f16.f16.f32 "
        "{%0,%1,%2,%3}, {%4,%5,%6,%7}, {%8,%9}, {%0,%1,%2,%3};\n"
        : "+f"(c[0]), "+f"(c[1]), "+f"(c[2]), "+f"(c[3])
        : "r"(a0), "r"(a1), "r"(a2), "r"(a3), "r"(b0), "r"(b1));
}

__global__ __launch_bounds__(256, 3) void qjl_gemm_kernel(float* __restrict__ out)
{
    const int tid  = threadIdx.x;
    const int warp = tid >> 5;
    const int lane = tid & 31;
    const int h  = blockIdx.z;
    const int nb = blockIdx.y;     // 0..31, 64 q-rows each
    const int tb = blockIdx.x;     // 0..15, 128 tokens each

    const uint4* __restrict__ Ab = g_qA + (size_t)((h << 4) + (nb >> 1)) * 2048;
    const uint4* __restrict__ Bb = g_kB + (size_t)((h << 4) + tb) * 2048;
    const int ro = (nb & 1) * 64;            // row offset within the 128-row A tile

    const int warp_m = (warp & 1) * 32;
    const int warp_n = (warp >> 1) * 32;
    const int lr = lane >> 2;
    const int lc = lane & 3;

    float acc[2][4][4];
    #pragma unroll
    for (int mi = 0; mi < 2; mi++)
        #pragma unroll
        for (int ni = 0; ni < 4; ni++)
            #pragma unroll
            for (int v = 0; v < 4; v++) acc[mi][ni][v] = 0.f;

    #pragma unroll
    for (int kt = 0; kt < 4; kt++) {
        const uint4* Akt = Ab + kt * 512;
        const uint4* Bkt = Bb + kt * 512;

        // B fragments: one LDG.128 per ni covers both k8-steps
        uint4 bf[4];
        #pragma unroll
        for (int ni = 0; ni < 4; ni++)
            bf[ni] = Bkt[(warp_n + ni * 8 + lr) * 4 + lc];

        // A fragments (mi = 0,1)
        uint4 alo[2], ahi[2];
        #pragma unroll
        for (int mi = 0; mi < 2; mi++) {
            int row = ro + warp_m + mi * 16 + lr;
            alo[mi] = Akt[row * 4 + lc];
            ahi[mi] = Akt[(row + 8) * 4 + lc];
        }

        #pragma unroll
        for (int mi = 0; mi < 2; mi++)
            #pragma unroll
            for (int ni = 0; ni < 4; ni++) {
                mma_f16(acc[mi][ni], alo[mi].x, ahi[mi].x, alo[mi].y, ahi[mi].y,
                        bf[ni].x, bf[ni].y);
                mma_f16(acc[mi][ni], alo[mi].z, ahi[mi].z, alo[mi].w, ahi[mi].w,
                        bf[ni].z, bf[ni].w);
            }
    }

    // epilogue: token-permuted fragments -> 16B-contiguous STG.128 per lane.
    float* Og = out + ((size_t)h * N_ + nb * 64) * T_ + tb * 128;
    #pragma unroll
    for (int mi = 0; mi < 2; mi++) {
        int row = warp_m + mi * 16 + lr;
        #pragma unroll
        for (int j = 0; j < 2; j++) {
            int col = warp_n + 16 * j + 4 * lc;
            float4 v0 = make_float4(acc[mi][2*j][0], acc[mi][2*j][1],
                                    acc[mi][2*j+1][0], acc[mi][2*j+1][1]);
            float4 v1 = make_float4(acc[mi][2*j][2], acc[mi][2*j][3],
                                    acc[mi][2*j+1][2], acc[mi][2*j+1][3]);
            __stcs((float4*)(Og + (size_t)row * T_ + col), v0);
            __stcs((float4*)(Og + (size_t)(row + 8) * T_ + col), v1);
        }
    }
}

// ---------------------------------------------------------------------------
extern "C" void kernel_launch(void* const* d_in, const int* in_sizes, int n_in,
                              void* d_out, int out_size)
{
    const float* q  = (const float*)d_in[0];
    const float* ko = (const float*)d_in[1];
    const float* kq = (const float*)d_in[2];
    const float* G  = (const float*)d_in[3];
    float* out = (float*)d_out;

    const size_t smem_prep = (128 * SG_S + 128 * SE_S) * sizeof(float);
    cudaFuncSetAttribute(qjl_prep_kernel, cudaFuncAttributeMaxDynamicSharedMemorySize,
                         (int)smem_prep);

    qcvt_kernel<<<(H_ * N_ * 4) / 256, 256>>>(q);
    qjl_prep_kernel<<<dim3(T_ / 64, H_), 256, smem_prep>>>(ko, kq, G);
    qjl_gemm_kernel<<<dim3(T_ / 128, N_ / 64, H_), 256>>>(out);
}

// round 11
// speedup vs baseline: 3.1830x; 1.0599x over previous
#include <cuda_runtime.h>
#include <cuda_fp16.h>
#include <cstdint>

#define H_  32
#define N_  2048
#define T_  2048
#define D_  128
#define R_  64

// Fragment-permuted fp16 operand buffers:
//   g_qA: [h*16 + nb][kt(4)][row(128)][lc(4)] uint4 — row = output n (identity)
//   g_kB: same shape, but token t stored at fragment row rho(t) so that the
//         MMA output fragment becomes 16B-contiguous in the output:
//         rho(t) = (2*(t>>4) + ((t>>1)&1))*8 + ((t>>2)&3)*2 + (t&1)
__device__ __align__(16) uint4 g_qA[H_ * 16 * 4 * 128 * 4];   // 16.8 MB
__device__ __align__(16) uint4 g_kB[H_ * 16 * 4 * 128 * 4];   // 16.8 MB

// ---------------------------------------------------------------------------
// packed f32x2 helpers (Blackwell sm_100+ family, NOT 'a'-gated)
// ---------------------------------------------------------------------------
__device__ __forceinline__ uint64_t pack2(float lo, float hi) {
    uint64_t v; asm("mov.b64 %0, {%1, %2};" : "=l"(v) : "f"(lo), "f"(hi)); return v;
}
__device__ __forceinline__ void unpack2(uint64_t v, float& lo, float& hi) {
    asm("mov.b64 {%0, %1}, %2;" : "=f"(lo), "=f"(hi) : "l"(v));
}
__device__ __forceinline__ uint64_t ffma2(uint64_t a, uint64_t b, uint64_t c) {
    uint64_t d;
    asm("fma.rn.f32x2 %0, %1, %2, %3;" : "=l"(d) : "l"(a), "l"(b), "l"(c));
    return d;
}

__device__ __forceinline__ uint32_t h2u(__half2 h) {
    union { __half2 h; uint32_t u; } c; c.h = h; return c.u;
}

__device__ __forceinline__ void mma_f16(float* c,
                                        uint32_t a0, uint32_t a1, uint32_t a2, uint32_t a3,
                                        uint32_t b0, uint32_t b1) {
    asm volatile(
        "mma.sync.aligned.m16n8k16.row.col.f32.f16.f16.f32 "
        "{%0,%1,%2,%3}, {%4,%5,%6,%7}, {%8,%9}, {%0,%1,%2,%3};\n"
        : "+f"(c[0]), "+f"(c[1]), "+f"(c[2]), "+f"(c[3])
        : "r"(a0), "r"(a1), "r"(a2), "r"(a3), "r"(b0), "r"(b1));
}

// ---------------------------------------------------------------------------
// Fused prep + qcvt kernel.
//   blocks [0, 1024): per (head, 64-token chunk):
//     stage 1 (exact fp32): s[t,r] = sign(sum_d e[t,d]*G[d,r]) -> s16 fp16
//     stage 2 (tensor core): corr = s @ G16^T  (m=64 t, n=128 d, k=64 r)
//                 keff[t,d] = fp16(kq + corr/64) -> rho-permuted g_kB
//   blocks [1024, 1280): q -> fp16 fragment-permute into g_qA (4 chunks each)
// ---------------------------------------------------------------------------
#define SG_S  68     // sG  [128][68] fp32 (d, r)
#define SE_S  65     // sE  [128][65] fp32 (d, t)
#define S16S  72     // s16 [64][72] halves (t, r)   — aliases sE region
#define G16S  72     // G16 [128][72] halves (d, r)
#define PREP_SMEM ((128 * SG_S + 128 * SE_S) * 4 + 128 * G16S * 2)

__global__ __launch_bounds__(256, 2) void qjl_prep_fused(
    const float* __restrict__ k_orig,
    const float* __restrict__ k_quant,
    const float* __restrict__ G,
    const float* __restrict__ q)
{
    // ---------------- qcvt part ----------------
    if (blockIdx.x >= 1024) {
        const int b2  = blockIdx.x - 1024;
        const int tid = threadIdx.x;
        #pragma unroll
        for (int it = 0; it < 4; it++) {
            int idx = (b2 * 4 + it) * 256 + tid;
            int row = idx & 127;
            int kt  = (idx >> 7) & 3;
            int hb  = idx >> 9;
            const float4* src = (const float4*)q + ((size_t)hb * 128 + row) * 32 + kt * 8;
            float4 r[8];
            #pragma unroll
            for (int j = 0; j < 8; j++) r[j] = src[j];
            const float* f = (const float*)r;
            uint4* dst = g_qA + ((size_t)hb * 4 + kt) * 512 + row * 4;
            #pragma unroll
            for (int lc = 0; lc < 4; lc++) {
                uint4 o;
                o.x = h2u(__floats2half2_rn(f[2*(lc     )], f[2*(lc     ) + 1]));
                o.y = h2u(__floats2half2_rn(f[2*(lc + 4 )], f[2*(lc + 4 ) + 1]));
                o.z = h2u(__floats2half2_rn(f[2*(lc + 8 )], f[2*(lc + 8 ) + 1]));
                o.w = h2u(__floats2half2_rn(f[2*(lc + 12)], f[2*(lc + 12) + 1]));
                dst[lc] = o;
            }
        }
        return;
    }

    // ---------------- prep part ----------------
    extern __shared__ float sm[];
    float*  sG  = sm;                                    // [128][SG_S] fp32
    float*  sE  = sG + 128 * SG_S;                       // [128][SE_S] fp32
    __half* G16 = (__half*)(sE + 128 * SE_S);            // [128][G16S] fp16
    uint32_t* s16w = (uint32_t*)sE;                      // s16 as u32, aliases sE
    const uint32_t* G16w = (const uint32_t*)G16;

    const int tid  = threadIdx.x;
    const int lane = tid & 31;
    const int wrp  = tid >> 5;
    const int h    = blockIdx.x & 31;
    const int t0   = (blockIdx.x >> 5) * 64;

    // load G (fp32 for stage 1, fp16 for stage 2)
    for (int i = tid; i < D_ * R_; i += 256) {
        int d = i >> 6, r = i & 63;
        float g = G[i];
        sG[d * SG_S + r] = g;
        G16[d * G16S + r] = __float2half_rn(g);
    }
    const float* ko = k_orig  + ((size_t)h * T_ + t0) * D_;
    const float* kq = k_quant + ((size_t)h * T_ + t0) * D_;
    for (int i = tid; i < 64 * D_; i += 256) {
        int t = i >> 7, d = i & 127;
        sE[d * SE_S + t] = ko[t * D_ + d] - kq[t * D_ + d];
    }
    __syncthreads();

    // ---- stage 1 (exact fp32): s = sign(e @ G), written as fp16 pairs to s16
    {
        const int tc = tid & 63;
        const int rg = tid >> 6;
        uint64_t acc[8];
        #pragma unroll
        for (int i = 0; i < 8; i++) acc[i] = pack2(0.f, 0.f);
        for (int d = 0; d < D_; d++) {
            float ev = sE[d * SE_S + tc];
            uint64_t ev2 = pack2(ev, ev);
            const ulonglong2* gp = (const ulonglong2*)(sG + d * SG_S + rg * 16);
            #pragma unroll
            for (int v = 0; v < 4; v++) {
                ulonglong2 g2 = gp[v];
                acc[v*2+0] = ffma2(ev2, g2.x, acc[v*2+0]);
                acc[v*2+1] = ffma2(ev2, g2.y, acc[v*2+1]);
            }
        }
        __syncthreads();   // all sE reads done before s16 (alias) writes
        #pragma unroll
        for (int i = 0; i < 8; i++) {
            float a0, a1;
            unpack2(acc[i], a0, a1);
            float s0 = (a0 > 0.f) ? 1.f : ((a0 < 0.f) ? -1.f : 0.f);
            float s1 = (a1 > 0.f) ? 1.f : ((a1 < 0.f) ? -1.f : 0.f);
            // s16[t = tc][r = rg*16 + 2i, 2i+1]  (u32 index: stride 36)
            s16w[tc * (S16S/2) + rg * 8 + i] = h2u(__floats2half2_rn(s0, s1));
        }
    }
    __syncthreads();

    // ---- stage 2 (tensor core): corr[t,d] = sum_r s16[t,r] * G16[d,r]
    // 8 warps: mw = wrp&3 -> t-tile mw*16 ; nw = wrp>>2 -> d-tile nw*64
    {
        const int mw = wrp & 3;
        const int nw = wrp >> 2;
        const int lg = lane >> 2;      // 0..7
        const int lc = lane & 3;       // 0..3

        float acc[8][4];
        #pragma unroll
        for (int nt = 0; nt < 8; nt++)
            #pragma unroll
            for (int v = 0; v < 4; v++) acc[nt][v] = 0.f;

        #pragma unroll
        for (int ks = 0; ks < 4; ks++) {
            const int t = mw * 16 + lg;
            uint32_t a0 = s16w[ t      * 36 + ks * 8 + lc];
            uint32_t a1 = s16w[(t + 8) * 36 + ks * 8 + lc];
            uint32_t a2 = s16w[ t      * 36 + ks * 8 + 4 + lc];
            uint32_t a3 = s16w[(t + 8) * 36 + ks * 8 + 4 + lc];
            #pragma unroll
            for (int nt = 0; nt < 8; nt++) {
                int n = nw * 64 + nt * 8 + lg;
                uint32_t b0 = G16w[n * 36 + ks * 8 + lc];
                uint32_t b1 = G16w[n * 36 + ks * 8 + 4 + lc];
                mma_f16(acc[nt], a0, a1, a2, a3, b0, b1);
            }
        }

        // epilogue: keff = fp16(kq + corr/64), u32 pair store into g_kB
        const int tb = (h << 4) + (t0 >> 7);
        const float scale = 1.f / 64.f;
        #pragma unroll
        for (int nt = 0; nt < 8; nt++) {
            int d0  = nw * 64 + nt * 8 + 2 * lc;
            int kt  = d0 >> 5;
            int wv  = (d0 >> 1) & 15;
            int lcq = wv & 3;
            int p   = wv >> 2;
            uint32_t* outp = (uint32_t*)g_kB + ((size_t)(tb * 4 + kt) * 128) * 16
                           + lcq * 4 + p;
            #pragma unroll
            for (int hh = 0; hh < 2; hh++) {
                int t_loc = mw * 16 + lg + hh * 8;
                float c0 = acc[nt][hh * 2 + 0];
                float c1 = acc[nt][hh * 2 + 1];
                float2 kq2 = *(const float2*)(kq + (size_t)t_loc * D_ + d0);
                int tl  = (t0 & 127) + t_loc;
                int row = (2 * (tl >> 4) + ((tl >> 1) & 1)) * 8
                        + ((tl >> 2) & 3) * 2 + (tl & 1);          // rho(tl)
                outp[row * 16] = h2u(__floats2half2_rn(kq2.x + c0 * scale,
                                                       kq2.y + c1 * scale));
            }
        }
    }
}

// ---------------------------------------------------------------------------
// Main GEMM, smem-free, barrier-free. Block tile 64x128, 8 warps (2x4),
// warp tile 32x32, 3 CTAs/SM. B rows carry rho() -> STG.128 epilogue.
// ---------------------------------------------------------------------------
__global__ __launch_bounds__(256, 3) void qjl_gemm_kernel(float* __restrict__ out)
{
    const int tid  = threadIdx.x;
    const int warp = tid >> 5;
    const int lane = tid & 31;
    const int h  = blockIdx.z;
    const int nb = blockIdx.y;     // 0..31, 64 q-rows each
    const int tb = blockIdx.x;     // 0..15, 128 tokens each

    const uint4* __restrict__ Ab = g_qA + (size_t)((h << 4) + (nb >> 1)) * 2048;
    const uint4* __restrict__ Bb = g_kB + (size_t)((h << 4) + tb) * 2048;
    const int ro = (nb & 1) * 64;

    const int warp_m = (warp & 1) * 32;
    const int warp_n = (warp >> 1) * 32;
    const int lr = lane >> 2;
    const int lc = lane & 3;

    float acc[2][4][4];
    #pragma unroll
    for (int mi = 0; mi < 2; mi++)
        #pragma unroll
        for (int ni = 0; ni < 4; ni++)
            #pragma unroll
            for (int v = 0; v < 4; v++) acc[mi][ni][v] = 0.f;

    #pragma unroll
    for (int kt = 0; kt < 4; kt++) {
        const uint4* Akt = Ab + kt * 512;
        const uint4* Bkt = Bb + kt * 512;

        uint4 bf[4];
        #pragma unroll
        for (int ni = 0; ni < 4; ni++)
            bf[ni] = Bkt[(warp_n + ni * 8 + lr) * 4 + lc];

        uint4 alo[2], ahi[2];
        #pragma unroll
        for (int mi = 0; mi < 2; mi++) {
            int row = ro + warp_m + mi * 16 + lr;
            alo[mi] = Akt[row * 4 + lc];
            ahi[mi] = Akt[(row + 8) * 4 + lc];
        }

        #pragma unroll
        for (int mi = 0; mi < 2; mi++)
            #pragma unroll
            for (int ni = 0; ni < 4; ni++) {
                mma_f16(acc[mi][ni], alo[mi].x, ahi[mi].x, alo[mi].y, ahi[mi].y,
                        bf[ni].x, bf[ni].y);
                mma_f16(acc[mi][ni], alo[mi].z, ahi[mi].z, alo[mi].w, ahi[mi].w,
                        bf[ni].z, bf[ni].w);
            }
    }

    float* Og = out + ((size_t)h * N_ + nb * 64) * T_ + tb * 128;
    #pragma unroll
    for (int mi = 0; mi < 2; mi++) {
        int row = warp_m + mi * 16 + lr;
        #pragma unroll
        for (int j = 0; j < 2; j++) {
            int col = warp_n + 16 * j + 4 * lc;
            float4 v0 = make_float4(acc[mi][2*j][0], acc[mi][2*j][1],
                                    acc[mi][2*j+1][0], acc[mi][2*j+1][1]);
            float4 v1 = make_float4(acc[mi][2*j][2], acc[mi][2*j][3],
                                    acc[mi][2*j+1][2], acc[mi][2*j+1][3]);
            __stcs((float4*)(Og + (size_t)row * T_ + col), v0);
            __stcs((float4*)(Og + (size_t)(row + 8) * T_ + col), v1);
        }
    }
}

// ---------------------------------------------------------------------------
extern "C" void kernel_launch(void* const* d_in, const int* in_sizes, int n_in,
                              void* d_out, int out_size)
{
    const float* q  = (const float*)d_in[0];
    const float* ko = (const float*)d_in[1];
    const float* kq = (const float*)d_in[2];
    const float* G  = (const float*)d_in[3];
    float* out = (float*)d_out;

    cudaFuncSetAttribute(qjl_prep_fused, cudaFuncAttributeMaxDynamicSharedMemorySize,
                         (int)PREP_SMEM);

    qjl_prep_fused<<<1280, 256, PREP_SMEM>>>(ko, kq, G, q);
    qjl_gemm_kernel<<<dim3(T_ / 128, N_ / 64, H_), 256>>>(out);
}